// round 6
// baseline (speedup 1.0000x reference)
#include <cuda_runtime.h>
#include <cuda_bf16.h>
#include <cstdint>

// ---------------------------------------------------------------------------
// Problem constants (B=1024, D_IN=1024, D_H=4096, D_OUT=1024, SPARSITY=0.5)
// concat order: [sW1, sb1, sW2, sb2, sW3, sb3]
// n = 25175040, j = 12587520
// ---------------------------------------------------------------------------
#define NTOT   25175040
#define NTOT4  6293760
#define JRANK  12587520u

#define E0 4194304
#define E1 4198400
#define E2 20975616
#define E3 20979712
#define E4 25174016
#define F0 1048576
#define F1 1049600
#define F2 5243904
#define F3 5244928
#define F4 6293504

#define CAND_CAP (1<<20)

// ---------------------------------------------------------------------------
// Device scratch
// ---------------------------------------------------------------------------
__device__ __align__(256) __nv_bfloat16 g_wh[16777216];
__device__ __align__(256) __nv_bfloat16 g_wl[16777216];
__device__ __align__(256) __nv_bfloat16 g_xh[1048576],  g_xl[1048576];
__device__ __align__(256) __nv_bfloat16 g_h1h[4194304], g_h1l[4194304];
__device__ __align__(256) __nv_bfloat16 g_h2h[4194304], g_h2l[4194304];
__device__ __align__(256) float    g_mb[4096];
__device__ unsigned g_hist1[4096];
__device__ unsigned g_sel[16];   // 0:bin1 1:cum1 4:KT 8:tieth 9:candcnt
__device__ unsigned g_candk[CAND_CAP];
__device__ unsigned g_candi[CAND_CAP];

// ---------------------------------------------------------------------------
// PTX helpers (baseline ISA: cp.async / ldmatrix / mma.sync)
// ---------------------------------------------------------------------------
__device__ __forceinline__ uint32_t smem_u32(const void* p) {
    uint32_t a;
    asm("{ .reg .u64 t; cvta.to.shared.u64 t, %1; cvt.u32.u64 %0, t; }" : "=r"(a) : "l"(p));
    return a;
}
__device__ __forceinline__ void cp16(uint32_t dst, const void* src) {
    asm volatile("cp.async.cg.shared.global [%0], [%1], 16;" :: "r"(dst), "l"(src));
}
#define CP_COMMIT() asm volatile("cp.async.commit_group;" ::: "memory")

__device__ __forceinline__ void ldm_x4(uint32_t* r, uint32_t addr) {
    asm volatile("ldmatrix.sync.aligned.m8n8.x4.shared.b16 {%0,%1,%2,%3}, [%4];"
        : "=r"(r[0]), "=r"(r[1]), "=r"(r[2]), "=r"(r[3]) : "r"(addr));
}
__device__ __forceinline__ void mma_bf16(float* c, const uint32_t* a, const uint32_t* b) {
    asm volatile(
        "mma.sync.aligned.m16n8k16.row.col.f32.bf16.bf16.f32 "
        "{%0,%1,%2,%3}, {%4,%5,%6,%7}, {%8,%9}, {%0,%1,%2,%3};"
        : "+f"(c[0]), "+f"(c[1]), "+f"(c[2]), "+f"(c[3])
        : "r"(a[0]), "r"(a[1]), "r"(a[2]), "r"(a[3]), "r"(b[0]), "r"(b[1]));
}

// ---------------------------------------------------------------------------
// Selection
// ---------------------------------------------------------------------------
__device__ __forceinline__ unsigned f2key(float f) {
    unsigned u = __float_as_uint(f);
    return (u & 0x80000000u) ? ~u : (u | 0x80000000u);
}
__device__ __forceinline__ float4 fetch4(int i4,
    const float4* __restrict__ s0, const float4* __restrict__ s1,
    const float4* __restrict__ s2, const float4* __restrict__ s3,
    const float4* __restrict__ s4, const float4* __restrict__ s5)
{
    if (i4 < F0) return s0[i4];
    if (i4 < F1) return s1[i4 - F0];
    if (i4 < F2) return s2[i4 - F1];
    if (i4 < F3) return s3[i4 - F2];
    if (i4 < F4) return s4[i4 - F3];
    return s5[i4 - F4];
}

__global__ void k_zero() {
    int t = threadIdx.x;
    for (int i = t; i < 4096; i += 256) g_hist1[i] = 0;
    if (t < 16) g_sel[t] = 0;
}

// warp-aggregated smem atomics (hot-bin serialization fix)
__device__ __forceinline__ void hist_add(unsigned* h, unsigned bin, int lane) {
    unsigned act = __activemask();
    unsigned m = __match_any_sync(act, bin);
    if ((int)(__ffs(m) - 1) == lane) atomicAdd(&h[bin], __popc(m));
}

__global__ void k_hist1(
    const float4* __restrict__ s0, const float4* __restrict__ s1,
    const float4* __restrict__ s2, const float4* __restrict__ s3,
    const float4* __restrict__ s4, const float4* __restrict__ s5)
{
    __shared__ unsigned h[4096];
    for (int i = threadIdx.x; i < 4096; i += blockDim.x) h[i] = 0;
    __syncthreads();
    const int lane = threadIdx.x & 31;
    const int stride = gridDim.x * blockDim.x;
    for (int i4 = blockIdx.x * blockDim.x + threadIdx.x; i4 < NTOT4; i4 += stride) {
        float4 v = fetch4(i4, s0, s1, s2, s3, s4, s5);
        hist_add(h, f2key(v.x) >> 20, lane);
        hist_add(h, f2key(v.y) >> 20, lane);
        hist_add(h, f2key(v.z) >> 20, lane);
        hist_add(h, f2key(v.w) >> 20, lane);
    }
    __syncthreads();
    for (int i = threadIdx.x; i < 4096; i += blockDim.x) {
        unsigned c = h[i];
        if (c) atomicAdd(&g_hist1[i], c);
    }
}

__global__ void k_scan1() {
    __shared__ unsigned part[256];
    int t = threadIdx.x;
    unsigned s = 0;
    for (int i = 0; i < 16; i++) s += g_hist1[t * 16 + i];
    part[t] = s;
    __syncthreads();
    if (t == 0) {
        unsigned c = 0;
        int ch = 0;
        for (; ch < 255; ch++) { if (c + part[ch] > JRANK) break; c += part[ch]; }
        int b = ch * 16;
        for (;; b++) { unsigned hh = g_hist1[b]; if (c + hh > JRANK) break; c += hh; }
        g_sel[0] = (unsigned)b; g_sel[1] = c;
    }
}

__global__ void k_compact(
    const float4* __restrict__ s0, const float4* __restrict__ s1,
    const float4* __restrict__ s2, const float4* __restrict__ s3,
    const float4* __restrict__ s4, const float4* __restrict__ s5)
{
    const unsigned bin = g_sel[0];
    const int stride = gridDim.x * blockDim.x;
    for (int i4 = blockIdx.x * blockDim.x + threadIdx.x; i4 < NTOT4; i4 += stride) {
        float4 v = fetch4(i4, s0, s1, s2, s3, s4, s5);
        float vv[4] = {v.x, v.y, v.z, v.w};
        #pragma unroll
        for (int c = 0; c < 4; c++) {
            unsigned key = f2key(vv[c]);
            if ((key >> 20) == bin) {
                unsigned p = atomicAdd(&g_sel[9], 1u);
                if (p < CAND_CAP) { g_candk[p] = key; g_candi[p] = (unsigned)(i4 * 4 + c); }
            }
        }
    }
}

__global__ void k_finish() {
    __shared__ unsigned h[1024];
    __shared__ unsigned ties[2048];
    __shared__ unsigned sh_b2, sh_c2, sh_KT, sh_need, sh_tc;
    int t = threadIdx.x;
    unsigned cnt = g_sel[9]; if (cnt > CAND_CAP) cnt = CAND_CAP;

    h[t] = 0;
    if (t == 0) sh_tc = 0;
    __syncthreads();
    for (unsigned j = t; j < cnt; j += 1024) atomicAdd(&h[(g_candk[j] >> 10) & 1023u], 1u);
    __syncthreads();
    if (t == 0) {
        unsigned c = g_sel[1];
        int b = 0;
        for (;; b++) { if (c + h[b] > JRANK) break; c += h[b]; }
        sh_b2 = (unsigned)b; sh_c2 = c;
    }
    __syncthreads();
    unsigned b2 = sh_b2;
    h[t] = 0;
    __syncthreads();
    for (unsigned j = t; j < cnt; j += 1024) {
        unsigned k = g_candk[j];
        if (((k >> 10) & 1023u) == b2) atomicAdd(&h[k & 1023u], 1u);
    }
    __syncthreads();
    if (t == 0) {
        unsigned c = sh_c2;
        int b = 0;
        for (;; b++) { if (c + h[b] > JRANK) break; c += h[b]; }
        sh_KT = (g_sel[0] << 20) | (b2 << 10) | (unsigned)b;
        sh_need = JRANK - c;
    }
    __syncthreads();
    unsigned KT = sh_KT;
    for (unsigned j = t; j < cnt; j += 1024) {
        if (g_candk[j] == KT) {
            unsigned p = atomicAdd(&sh_tc, 1u);
            if (p < 2048) ties[p] = g_candi[j];
        }
    }
    __syncthreads();
    if (t == 0) {
        int n = (int)sh_tc; if (n > 2048) n = 2048;
        for (int i = 1; i < n; i++) {
            unsigned v = ties[i]; int j = i - 1;
            while (j >= 0 && ties[j] > v) { ties[j + 1] = ties[j]; j--; }
            ties[j + 1] = v;
        }
        g_sel[4] = KT;
        g_sel[8] = (sh_need < (unsigned)n) ? ties[sh_need] : 0xFFFFFFFFu;
    }
}

// ---------------------------------------------------------------------------
// Apply / split
// ---------------------------------------------------------------------------
__global__ void k_applyw(const float4* __restrict__ w, const float4* __restrict__ s,
                         __nv_bfloat16* __restrict__ oh, __nv_bfloat16* __restrict__ ol,
                         int n4, unsigned flatoff)
{
    const unsigned KT = g_sel[4], tieth = g_sel[8];
    int i = blockIdx.x * blockDim.x + threadIdx.x;
    if (i >= n4) return;
    float4 wv = w[i], sv = s[i];
    float sa[4] = {sv.x, sv.y, sv.z, sv.w};
    float wa[4] = {wv.x, wv.y, wv.z, wv.w};
    unsigned fb = flatoff + 4u * (unsigned)i;
    ushort4 uh, ul;
    unsigned short* ph = (unsigned short*)&uh;
    unsigned short* pl = (unsigned short*)&ul;
    #pragma unroll
    for (int c = 0; c < 4; c++) {
        unsigned key = f2key(sa[c]);
        bool keep = (key > KT) || (key == KT && (fb + c) >= tieth);
        float v = keep ? wa[c] : 0.f;
        __nv_bfloat16 hi = __float2bfloat16(v);
        __nv_bfloat16 lo = __float2bfloat16(v - __bfloat162float(hi));
        ph[c] = __bfloat16_as_ushort(hi);
        pl[c] = __bfloat16_as_ushort(lo);
    }
    *(ushort4*)(oh + 4 * (size_t)i) = uh;
    *(ushort4*)(ol + 4 * (size_t)i) = ul;
}

__global__ void k_applyb(const float4* __restrict__ w, const float4* __restrict__ s,
                         float4* __restrict__ dst, int n4, unsigned flatoff)
{
    const unsigned KT = g_sel[4], tieth = g_sel[8];
    int i = blockIdx.x * blockDim.x + threadIdx.x;
    if (i >= n4) return;
    float4 wv = w[i], sv = s[i];
    float sa[4] = {sv.x, sv.y, sv.z, sv.w};
    float wa[4] = {wv.x, wv.y, wv.z, wv.w};
    unsigned fb = flatoff + 4u * (unsigned)i;
    #pragma unroll
    for (int c = 0; c < 4; c++) {
        unsigned key = f2key(sa[c]);
        bool keep = (key > KT) || (key == KT && (fb + c) >= tieth);
        if (!keep) wa[c] = 0.f;
    }
    dst[i] = make_float4(wa[0], wa[1], wa[2], wa[3]);
}

__global__ void k_split(const float4* __restrict__ x,
                        __nv_bfloat16* __restrict__ oh, __nv_bfloat16* __restrict__ ol, int n4)
{
    int i = blockIdx.x * blockDim.x + threadIdx.x;
    if (i >= n4) return;
    float4 v = x[i];
    float va[4] = {v.x, v.y, v.z, v.w};
    ushort4 uh, ul;
    unsigned short* ph = (unsigned short*)&uh;
    unsigned short* pl = (unsigned short*)&ul;
    #pragma unroll
    for (int c = 0; c < 4; c++) {
        __nv_bfloat16 hi = __float2bfloat16(va[c]);
        __nv_bfloat16 lo = __float2bfloat16(va[c] - __bfloat162float(hi));
        ph[c] = __bfloat16_as_ushort(hi);
        pl[c] = __bfloat16_as_ushort(lo);
    }
    *(ushort4*)(oh + 4 * (size_t)i) = uh;
    *(ushort4*)(ol + 4 * (size_t)i) = ul;
}

// ---------------------------------------------------------------------------
// mma.sync bf16 split GEMM: C[M,N] = A[M,K]*B[N,K]^T + bias
//   C ~= Ahi*Bhi + Alo*Bhi + Ahi*Blo   (fp32 accumulate)
// CTA tile 128 x BN, BK=32, 256 threads (8 warps, 2m x 4n).
// 2 CTAs/SM (launch_bounds 256,2): BN=128 -> 2-stage (80KB), BN=64 -> 3-stage (90KB).
// Row stride 80B (64B data + 16B pad) -> conflict-free ldmatrix.
// MODE 0: relu + bf16 hi/lo outputs; MODE 1: fp32 output.
// ---------------------------------------------------------------------------
#define ROWB   80
#define ATILE  10240                   // 128 * 80

template<int ROWS>
__device__ __forceinline__ void stage_tile(const __nv_bfloat16* __restrict__ g,
                                           int row0, int k0, int K, uint32_t sdst)
{
    int tid = threadIdx.x;
    #pragma unroll
    for (int i = 0; i < ROWS / 64; i++) {     // ROWS*4 cp ops / 256 threads
        int s = tid + (i << 8);
        int r = s >> 2, sub = s & 3;
        cp16(sdst + (uint32_t)(r * ROWB + sub * 16),
             g + (size_t)(row0 + r) * K + k0 + sub * 8);
    }
}

template<int BN, int MODE>
__global__ void __launch_bounds__(256, 2) k_mgemm(
    const __nv_bfloat16* __restrict__ Ah, const __nv_bfloat16* __restrict__ Al,
    const __nv_bfloat16* __restrict__ Bh, const __nv_bfloat16* __restrict__ Bl,
    const float* __restrict__ bias,
    __nv_bfloat16* __restrict__ Oh, __nv_bfloat16* __restrict__ Ol,
    float* __restrict__ Of, int N, int K)
{
    constexpr int BTILE  = BN * ROWB;
    constexpr int STAGEB = 2 * ATILE + 2 * BTILE;
    constexpr int NSTAGE = (BN == 128) ? 2 : 3;
    constexpr int WN     = BN / 4;       // warp n extent
    constexpr int G      = WN / 8;       // 8-col groups per warp
    constexpr int PMAX   = (WN + 15) / 16;

    extern __shared__ char smem[];
    const uint32_t sb = smem_u32(smem);
    const int tid = threadIdx.x, lane = tid & 31, wid = tid >> 5;
    const int wm = wid & 1, wn = wid >> 1;
    const int bm = blockIdx.y << 7;
    const int bn = blockIdx.x * BN;

    float acc[4][G][4];
    #pragma unroll
    for (int f = 0; f < 4; f++)
        #pragma unroll
        for (int g = 0; g < G; g++)
            #pragma unroll
            for (int v = 0; v < 4; v++) acc[f][g][v] = 0.f;

    const int nc = K >> 5;

    // prologue: stage chunks 0,1
    #pragma unroll
    for (int pi = 0; pi < 2; pi++) {
        uint32_t sd = sb + (uint32_t)pi * STAGEB;
        stage_tile<128>(Ah, bm, pi * 32, K, sd);
        stage_tile<128>(Al, bm, pi * 32, K, sd + ATILE);
        stage_tile<BN> (Bh, bn, pi * 32, K, sd + 2 * ATILE);
        stage_tile<BN> (Bl, bn, pi * 32, K, sd + 2 * ATILE + BTILE);
        CP_COMMIT();
    }

    const int arow  = wm * 64 + (lane & 15);
    const int acolb = (lane >> 4) * 16;                      // bytes
    const int brow  = wn * WN + (lane & 7) + (((lane >> 4) & 1) << 3);
    const int bcolb = ((lane >> 3) & 1) * 16;                // bytes

    for (int i = 0; i < nc; i++) {
        if (i < nc - 1) asm volatile("cp.async.wait_group 1;" ::: "memory");
        else            asm volatile("cp.async.wait_group 0;" ::: "memory");
        __syncthreads();

        const uint32_t base = sb + (uint32_t)(i % NSTAGE) * STAGEB;

        if (NSTAGE == 3 && i + 2 < nc) {
            // 3-stage: prefetch before compute, single sync per chunk
            uint32_t sd = sb + (uint32_t)((i + 2) % NSTAGE) * STAGEB;
            int k0 = (i + 2) << 5;
            stage_tile<128>(Ah, bm, k0, K, sd);
            stage_tile<128>(Al, bm, k0, K, sd + ATILE);
            stage_tile<BN> (Bh, bn, k0, K, sd + 2 * ATILE);
            stage_tile<BN> (Bl, bn, k0, K, sd + 2 * ATILE + BTILE);
            CP_COMMIT();
        }

        #pragma unroll
        for (int kk = 0; kk < 2; kk++) {
            uint32_t Bhf[PMAX][4], Blf[PMAX][4];
            const uint32_t bk = (uint32_t)(kk * 32) + bcolb;
            #pragma unroll
            for (int p = 0; p < PMAX; p++) {
                uint32_t rb = base + 2u * ATILE + (uint32_t)((brow + p * 16) * ROWB) + bk;
                ldm_x4(Bhf[p], rb);
                ldm_x4(Blf[p], rb + BTILE);
            }
            const uint32_t ak = (uint32_t)(kk * 32) + acolb;
            #pragma unroll
            for (int f = 0; f < 4; f++) {
                uint32_t Ahf[4], Alf[4];
                uint32_t ra = base + (uint32_t)((arow + f * 16) * ROWB) + ak;
                ldm_x4(Ahf, ra);
                ldm_x4(Alf, ra + ATILE);
                #pragma unroll
                for (int g = 0; g < G; g++) {
                    const uint32_t* bh = &Bhf[g >> 1][(g & 1) << 1];
                    const uint32_t* bl = &Blf[g >> 1][(g & 1) << 1];
                    mma_bf16(acc[f][g], Ahf, bh);
                    mma_bf16(acc[f][g], Alf, bh);
                    mma_bf16(acc[f][g], Ahf, bl);
                }
            }
        }

        if (NSTAGE == 2 && i + 2 < nc) {
            // 2-stage: prefetch into the buffer just consumed
            __syncthreads();
            uint32_t sd = base;
            int k0 = (i + 2) << 5;
            stage_tile<128>(Ah, bm, k0, K, sd);
            stage_tile<128>(Al, bm, k0, K, sd + ATILE);
            stage_tile<BN> (Bh, bn, k0, K, sd + 2 * ATILE);
            stage_tile<BN> (Bl, bn, k0, K, sd + 2 * ATILE + BTILE);
            CP_COMMIT();
        }
    }

    // epilogue: bias (+relu), direct global stores
    #pragma unroll
    for (int f = 0; f < 4; f++) {
        #pragma unroll
        for (int g = 0; g < G; g++) {
            int r0 = bm + wm * 64 + f * 16 + (lane >> 2);
            int c0 = bn + wn * WN + g * 8 + ((lane & 3) << 1);
            float bv0 = bias[c0], bv1 = bias[c0 + 1];
            #pragma unroll
            for (int h = 0; h < 2; h++) {
                int r = r0 + h * 8;
                float v0 = acc[f][g][2 * h + 0] + bv0;
                float v1 = acc[f][g][2 * h + 1] + bv1;
                if (MODE == 0) {
                    v0 = fmaxf(v0, 0.f); v1 = fmaxf(v1, 0.f);
                    __nv_bfloat16 h0 = __float2bfloat16(v0), h1 = __float2bfloat16(v1);
                    __nv_bfloat16 l0 = __float2bfloat16(v0 - __bfloat162float(h0));
                    __nv_bfloat16 l1 = __float2bfloat16(v1 - __bfloat162float(h1));
                    ushort2 uh = make_ushort2(__bfloat16_as_ushort(h0), __bfloat16_as_ushort(h1));
                    ushort2 ul = make_ushort2(__bfloat16_as_ushort(l0), __bfloat16_as_ushort(l1));
                    *(ushort2*)(Oh + (size_t)r * N + c0) = uh;
                    *(ushort2*)(Ol + (size_t)r * N + c0) = ul;
                } else {
                    float2 o = make_float2(v0, v1);
                    *(float2*)(Of + (size_t)r * N + c0) = o;
                }
            }
        }
    }
}

// ---------------------------------------------------------------------------
// Launch
// ---------------------------------------------------------------------------
extern "C" void kernel_launch(void* const* d_in, const int* in_sizes, int n_in,
                              void* d_out, int out_size)
{
    const float* x  = (const float*)d_in[0];
    const float* W1 = (const float*)d_in[1];
    const float* b1 = (const float*)d_in[2];
    const float* W2 = (const float*)d_in[3];
    const float* b2 = (const float*)d_in[4];
    const float* W3 = (const float*)d_in[5];
    const float* b3 = (const float*)d_in[6];
    const float4* s0 = (const float4*)d_in[7];
    const float4* s1 = (const float4*)d_in[8];
    const float4* s2 = (const float4*)d_in[9];
    const float4* s3 = (const float4*)d_in[10];
    const float4* s4 = (const float4*)d_in[11];
    const float4* s5 = (const float4*)d_in[12];

    void* p;
    cudaGetSymbolAddress(&p, g_wh);  __nv_bfloat16* wh  = (__nv_bfloat16*)p;
    cudaGetSymbolAddress(&p, g_wl);  __nv_bfloat16* wl  = (__nv_bfloat16*)p;
    cudaGetSymbolAddress(&p, g_xh);  __nv_bfloat16* xh  = (__nv_bfloat16*)p;
    cudaGetSymbolAddress(&p, g_xl);  __nv_bfloat16* xl  = (__nv_bfloat16*)p;
    cudaGetSymbolAddress(&p, g_h1h); __nv_bfloat16* h1h = (__nv_bfloat16*)p;
    cudaGetSymbolAddress(&p, g_h1l); __nv_bfloat16* h1l = (__nv_bfloat16*)p;
    cudaGetSymbolAddress(&p, g_h2h); __nv_bfloat16* h2h = (__nv_bfloat16*)p;
    cudaGetSymbolAddress(&p, g_h2l); __nv_bfloat16* h2l = (__nv_bfloat16*)p;
    cudaGetSymbolAddress(&p, g_mb);  float* mb = (float*)p;

    const int SM128 = 2 * (2 * ATILE + 2 * 128 * ROWB);   // 81920
    const int SM64  = 3 * (2 * ATILE + 2 * 64  * ROWB);   // 92160
    cudaFuncSetAttribute((const void*)k_mgemm<128, 0>, cudaFuncAttributeMaxDynamicSharedMemorySize, SM128);
    cudaFuncSetAttribute((const void*)k_mgemm<64, 1>,  cudaFuncAttributeMaxDynamicSharedMemorySize, SM64);

    // ---- selection ----
    k_zero<<<1, 256>>>();
    k_hist1<<<1024, 256>>>(s0, s1, s2, s3, s4, s5);
    k_scan1<<<1, 256>>>();
    k_compact<<<1024, 256>>>(s0, s1, s2, s3, s4, s5);
    k_finish<<<1, 1024>>>();

    // ---- x split ----
    k_split<<<1024, 256>>>((const float4*)x, xh, xl, 262144);

    // ---- layer 1 ----
    k_applyw<<<4096, 256>>>((const float4*)W1, s0, wh, wl, 1048576, 0u);
    k_applyb<<<4, 256>>>((const float4*)b1, s1, (float4*)mb, 1024, (unsigned)E0);
    k_mgemm<128, 0><<<dim3(32, 8), 256, SM128>>>(xh, xl, wh, wl, mb, h1h, h1l, nullptr, 4096, 1024);

    // ---- layer 2 ----
    k_applyw<<<16384, 256>>>((const float4*)W2, s2, wh, wl, 4194304, (unsigned)E1);
    k_applyb<<<4, 256>>>((const float4*)b2, s3, (float4*)mb, 1024, (unsigned)E2);
    k_mgemm<128, 0><<<dim3(32, 8), 256, SM128>>>(h1h, h1l, wh, wl, mb, h2h, h2l, nullptr, 4096, 4096);

    // ---- layer 3 ----
    k_applyw<<<4096, 256>>>((const float4*)W3, s4, wh, wl, 1048576, (unsigned)E3);
    k_applyb<<<1, 256>>>((const float4*)b3, s5, (float4*)mb, 256, (unsigned)E4);
    k_mgemm<64, 1><<<dim3(16, 8), 256, SM64>>>(h2h, h2l, wh, wl, mb, nullptr, nullptr, (float*)d_out, 1024, 4096);
}

// round 7
// speedup vs baseline: 1.0641x; 1.0641x over previous
#include <cuda_runtime.h>
#include <cuda_bf16.h>
#include <cstdint>

// ---------------------------------------------------------------------------
// Problem constants (B=1024, D_IN=1024, D_H=4096, D_OUT=1024, SPARSITY=0.5)
// concat order: [sW1, sb1, sW2, sb2, sW3, sb3]
// n = 25175040, j = 12587520
// ---------------------------------------------------------------------------
#define NTOT   25175040
#define NTOT4  6293760
#define JRANK  12587520u

#define E0 4194304
#define E1 4198400
#define E2 20975616
#define E3 20979712
#define E4 25174016
#define F0 1048576
#define F1 1049600
#define F2 5243904
#define F3 5244928
#define F4 6293504

#define CAND_CAP (1<<20)

// ---------------------------------------------------------------------------
// Device scratch
// ---------------------------------------------------------------------------
__device__ __align__(256) __nv_bfloat16 g_wh[16777216];
__device__ __align__(256) __nv_bfloat16 g_wl[16777216];
__device__ __align__(256) __nv_bfloat16 g_xh[1048576],  g_xl[1048576];
__device__ __align__(256) __nv_bfloat16 g_h1h[4194304], g_h1l[4194304];
__device__ __align__(256) __nv_bfloat16 g_h2h[4194304], g_h2l[4194304];
__device__ __align__(256) float    g_p0[1048576], g_p1[1048576];   // layer3 split-K partials
__device__ __align__(256) float    g_mb[4096];
__device__ unsigned g_hist1[4096];
__device__ unsigned g_sel[16];   // 0:bin1 1:cum1 4:KT 8:tieth 9:candcnt
__device__ unsigned g_candk[CAND_CAP];
__device__ unsigned g_candi[CAND_CAP];

// ---------------------------------------------------------------------------
// PTX helpers (baseline ISA only: cp.async / ldmatrix / mma.sync)
// ---------------------------------------------------------------------------
__device__ __forceinline__ uint32_t smem_u32(const void* p) {
    uint32_t a;
    asm("{ .reg .u64 t; cvta.to.shared.u64 t, %1; cvt.u32.u64 %0, t; }" : "=r"(a) : "l"(p));
    return a;
}
__device__ __forceinline__ void cp16(uint32_t dst, const void* src) {
    asm volatile("cp.async.cg.shared.global [%0], [%1], 16;" :: "r"(dst), "l"(src));
}
#define CP_COMMIT() asm volatile("cp.async.commit_group;" ::: "memory")

__device__ __forceinline__ void ldm_x4(uint32_t* r, uint32_t addr) {
    asm volatile("ldmatrix.sync.aligned.m8n8.x4.shared.b16 {%0,%1,%2,%3}, [%4];"
        : "=r"(r[0]), "=r"(r[1]), "=r"(r[2]), "=r"(r[3]) : "r"(addr));
}
__device__ __forceinline__ void mma_bf16(float* c, const uint32_t* a, const uint32_t* b) {
    asm volatile(
        "mma.sync.aligned.m16n8k16.row.col.f32.bf16.bf16.f32 "
        "{%0,%1,%2,%3}, {%4,%5,%6,%7}, {%8,%9}, {%0,%1,%2,%3};"
        : "+f"(c[0]), "+f"(c[1]), "+f"(c[2]), "+f"(c[3])
        : "r"(a[0]), "r"(a[1]), "r"(a[2]), "r"(a[3]), "r"(b[0]), "r"(b[1]));
}

// ---------------------------------------------------------------------------
// Selection
// ---------------------------------------------------------------------------
__device__ __forceinline__ unsigned f2key(float f) {
    unsigned u = __float_as_uint(f);
    return (u & 0x80000000u) ? ~u : (u | 0x80000000u);
}
__device__ __forceinline__ float4 fetch4(int i4,
    const float4* __restrict__ s0, const float4* __restrict__ s1,
    const float4* __restrict__ s2, const float4* __restrict__ s3,
    const float4* __restrict__ s4, const float4* __restrict__ s5)
{
    if (i4 < F0) return s0[i4];
    if (i4 < F1) return s1[i4 - F0];
    if (i4 < F2) return s2[i4 - F1];
    if (i4 < F3) return s3[i4 - F2];
    if (i4 < F4) return s4[i4 - F3];
    return s5[i4 - F4];
}

__global__ void k_zero() {
    int t = threadIdx.x;
    for (int i = t; i < 4096; i += 256) g_hist1[i] = 0;
    if (t < 16) g_sel[t] = 0;
}

// warp-aggregated smem atomics (hot-bin serialization fix)
__device__ __forceinline__ void hist_add(unsigned* h, unsigned bin, int lane) {
    unsigned act = __activemask();
    unsigned m = __match_any_sync(act, bin);
    if ((int)(__ffs(m) - 1) == lane) atomicAdd(&h[bin], __popc(m));
}

__global__ void k_hist1(
    const float4* __restrict__ s0, const float4* __restrict__ s1,
    const float4* __restrict__ s2, const float4* __restrict__ s3,
    const float4* __restrict__ s4, const float4* __restrict__ s5)
{
    __shared__ unsigned h[4096];
    for (int i = threadIdx.x; i < 4096; i += blockDim.x) h[i] = 0;
    __syncthreads();
    const int lane = threadIdx.x & 31;
    const int stride = gridDim.x * blockDim.x;
    for (int i4 = blockIdx.x * blockDim.x + threadIdx.x; i4 < NTOT4; i4 += stride) {
        float4 v = fetch4(i4, s0, s1, s2, s3, s4, s5);
        hist_add(h, f2key(v.x) >> 20, lane);
        hist_add(h, f2key(v.y) >> 20, lane);
        hist_add(h, f2key(v.z) >> 20, lane);
        hist_add(h, f2key(v.w) >> 20, lane);
    }
    __syncthreads();
    for (int i = threadIdx.x; i < 4096; i += blockDim.x) {
        unsigned c = h[i];
        if (c) atomicAdd(&g_hist1[i], c);
    }
}

__global__ void k_scan1() {
    __shared__ unsigned part[256];
    int t = threadIdx.x;
    unsigned s = 0;
    for (int i = 0; i < 16; i++) s += g_hist1[t * 16 + i];
    part[t] = s;
    __syncthreads();
    if (t == 0) {
        unsigned c = 0;
        int ch = 0;
        for (; ch < 255; ch++) { if (c + part[ch] > JRANK) break; c += part[ch]; }
        int b = ch * 16;
        for (;; b++) { unsigned hh = g_hist1[b]; if (c + hh > JRANK) break; c += hh; }
        g_sel[0] = (unsigned)b; g_sel[1] = c;
    }
}

__global__ void k_compact(
    const float4* __restrict__ s0, const float4* __restrict__ s1,
    const float4* __restrict__ s2, const float4* __restrict__ s3,
    const float4* __restrict__ s4, const float4* __restrict__ s5)
{
    const unsigned bin = g_sel[0];
    const int stride = gridDim.x * blockDim.x;
    for (int i4 = blockIdx.x * blockDim.x + threadIdx.x; i4 < NTOT4; i4 += stride) {
        float4 v = fetch4(i4, s0, s1, s2, s3, s4, s5);
        float vv[4] = {v.x, v.y, v.z, v.w};
        #pragma unroll
        for (int c = 0; c < 4; c++) {
            unsigned key = f2key(vv[c]);
            if ((key >> 20) == bin) {
                unsigned p = atomicAdd(&g_sel[9], 1u);
                if (p < CAND_CAP) { g_candk[p] = key; g_candi[p] = (unsigned)(i4 * 4 + c); }
            }
        }
    }
}

__global__ void k_finish() {
    __shared__ unsigned h[1024];
    __shared__ unsigned ties[2048];
    __shared__ unsigned sh_b2, sh_c2, sh_KT, sh_need, sh_tc;
    int t = threadIdx.x;
    unsigned cnt = g_sel[9]; if (cnt > CAND_CAP) cnt = CAND_CAP;

    h[t] = 0;
    if (t == 0) sh_tc = 0;
    __syncthreads();
    for (unsigned j = t; j < cnt; j += 1024) atomicAdd(&h[(g_candk[j] >> 10) & 1023u], 1u);
    __syncthreads();
    if (t == 0) {
        unsigned c = g_sel[1];
        int b = 0;
        for (;; b++) { if (c + h[b] > JRANK) break; c += h[b]; }
        sh_b2 = (unsigned)b; sh_c2 = c;
    }
    __syncthreads();
    unsigned b2 = sh_b2;
    h[t] = 0;
    __syncthreads();
    for (unsigned j = t; j < cnt; j += 1024) {
        unsigned k = g_candk[j];
        if (((k >> 10) & 1023u) == b2) atomicAdd(&h[k & 1023u], 1u);
    }
    __syncthreads();
    if (t == 0) {
        unsigned c = sh_c2;
        int b = 0;
        for (;; b++) { if (c + h[b] > JRANK) break; c += h[b]; }
        sh_KT = (g_sel[0] << 20) | (b2 << 10) | (unsigned)b;
        sh_need = JRANK - c;
    }
    __syncthreads();
    unsigned KT = sh_KT;
    for (unsigned j = t; j < cnt; j += 1024) {
        if (g_candk[j] == KT) {
            unsigned p = atomicAdd(&sh_tc, 1u);
            if (p < 2048) ties[p] = g_candi[j];
        }
    }
    __syncthreads();
    if (t == 0) {
        int n = (int)sh_tc; if (n > 2048) n = 2048;
        for (int i = 1; i < n; i++) {
            unsigned v = ties[i]; int j = i - 1;
            while (j >= 0 && ties[j] > v) { ties[j + 1] = ties[j]; j--; }
            ties[j + 1] = v;
        }
        g_sel[4] = KT;
        g_sel[8] = (sh_need < (unsigned)n) ? ties[sh_need] : 0xFFFFFFFFu;
    }
}

// ---------------------------------------------------------------------------
// Apply / split
// ---------------------------------------------------------------------------
__global__ void k_applyw(const float4* __restrict__ w, const float4* __restrict__ s,
                         __nv_bfloat16* __restrict__ oh, __nv_bfloat16* __restrict__ ol,
                         int n4, unsigned flatoff)
{
    const unsigned KT = g_sel[4], tieth = g_sel[8];
    int i = blockIdx.x * blockDim.x + threadIdx.x;
    if (i >= n4) return;
    float4 wv = w[i], sv = s[i];
    float sa[4] = {sv.x, sv.y, sv.z, sv.w};
    float wa[4] = {wv.x, wv.y, wv.z, wv.w};
    unsigned fb = flatoff + 4u * (unsigned)i;
    ushort4 uh, ul;
    unsigned short* ph = (unsigned short*)&uh;
    unsigned short* pl = (unsigned short*)&ul;
    #pragma unroll
    for (int c = 0; c < 4; c++) {
        unsigned key = f2key(sa[c]);
        bool keep = (key > KT) || (key == KT && (fb + c) >= tieth);
        float v = keep ? wa[c] : 0.f;
        __nv_bfloat16 hi = __float2bfloat16(v);
        __nv_bfloat16 lo = __float2bfloat16(v - __bfloat162float(hi));
        ph[c] = __bfloat16_as_ushort(hi);
        pl[c] = __bfloat16_as_ushort(lo);
    }
    *(ushort4*)(oh + 4 * (size_t)i) = uh;
    *(ushort4*)(ol + 4 * (size_t)i) = ul;
}

__global__ void k_applyb(const float4* __restrict__ w, const float4* __restrict__ s,
                         float4* __restrict__ dst, int n4, unsigned flatoff)
{
    const unsigned KT = g_sel[4], tieth = g_sel[8];
    int i = blockIdx.x * blockDim.x + threadIdx.x;
    if (i >= n4) return;
    float4 wv = w[i], sv = s[i];
    float sa[4] = {sv.x, sv.y, sv.z, sv.w};
    float wa[4] = {wv.x, wv.y, wv.z, wv.w};
    unsigned fb = flatoff + 4u * (unsigned)i;
    #pragma unroll
    for (int c = 0; c < 4; c++) {
        unsigned key = f2key(sa[c]);
        bool keep = (key > KT) || (key == KT && (fb + c) >= tieth);
        if (!keep) wa[c] = 0.f;
    }
    dst[i] = make_float4(wa[0], wa[1], wa[2], wa[3]);
}

__global__ void k_split(const float4* __restrict__ x,
                        __nv_bfloat16* __restrict__ oh, __nv_bfloat16* __restrict__ ol, int n4)
{
    int i = blockIdx.x * blockDim.x + threadIdx.x;
    if (i >= n4) return;
    float4 v = x[i];
    float va[4] = {v.x, v.y, v.z, v.w};
    ushort4 uh, ul;
    unsigned short* ph = (unsigned short*)&uh;
    unsigned short* pl = (unsigned short*)&ul;
    #pragma unroll
    for (int c = 0; c < 4; c++) {
        __nv_bfloat16 hi = __float2bfloat16(va[c]);
        __nv_bfloat16 lo = __float2bfloat16(va[c] - __bfloat162float(hi));
        ph[c] = __bfloat16_as_ushort(hi);
        pl[c] = __bfloat16_as_ushort(lo);
    }
    *(ushort4*)(oh + 4 * (size_t)i) = uh;
    *(ushort4*)(ol + 4 * (size_t)i) = ul;
}

// layer3 reduce: out = p0 + p1 + bias
__global__ void k_reduce3(float4* __restrict__ out, const float4* __restrict__ p0,
                          const float4* __restrict__ p1, const float* __restrict__ bias)
{
    int i = blockIdx.x * blockDim.x + threadIdx.x;   // of 262144 float4s, N=1024
    float4 a = p0[i], b = p1[i];
    int c0 = (i << 2) & 1023;
    float4 o;
    o.x = a.x + b.x + bias[c0];
    o.y = a.y + b.y + bias[c0 + 1];
    o.z = a.z + b.z + bias[c0 + 2];
    o.w = a.w + b.w + bias[c0 + 3];
    out[i] = o;
}

// ---------------------------------------------------------------------------
// mma.sync bf16 split GEMM: C[M,N] = A[M,K]*B[N,K]^T + bias
//   C ~= Ahi*Bhi + Alo*Bhi + Ahi*Blo   (fp32 accumulate)
// CTA tile 128x128, BK=64, 256 threads (8 warps, 2m x 4n, warp tile 64x32)
// Row-padded SMEM (144B stride), double-buffered cp.async (R5 measured config).
// MODE 0: relu + bf16 hi/lo outputs; MODE 2: split-K fp32 partial (blockIdx.z half).
// ---------------------------------------------------------------------------
#define ROWB    144
#define TILEB   18432          // 128 * 144
#define BUFB    73728          // 4 tiles
#define MG_SMEM 147456         // 2 buffers

__device__ __forceinline__ void stage_tile(const __nv_bfloat16* __restrict__ g,
                                           int row0, int k0, int ld, uint32_t sdst)
{
    int tid = threadIdx.x;
    // 128 rows x 64 bf16 = 128 rows x 8 chunks of 16B = 1024 cp.async ops
    #pragma unroll
    for (int i = 0; i < 4; i++) {
        int s = tid + (i << 8);
        int r = s >> 3, sub = s & 7;
        cp16(sdst + (uint32_t)(r * ROWB + sub * 16),
             g + (size_t)(row0 + r) * ld + k0 + sub * 8);
    }
}

__device__ __forceinline__ void stage_buf(
    const __nv_bfloat16* Ah, const __nv_bfloat16* Al,
    const __nv_bfloat16* Bh, const __nv_bfloat16* Bl,
    int bm, int bn, int k0, int ld, uint32_t sbase)
{
    stage_tile(Ah, bm, k0, ld, sbase);
    stage_tile(Al, bm, k0, ld, sbase + TILEB);
    stage_tile(Bh, bn, k0, ld, sbase + 2 * TILEB);
    stage_tile(Bl, bn, k0, ld, sbase + 3 * TILEB);
}

template<int MODE>
__global__ void __launch_bounds__(256, 1) k_mgemm(
    const __nv_bfloat16* __restrict__ Ah, const __nv_bfloat16* __restrict__ Al,
    const __nv_bfloat16* __restrict__ Bh, const __nv_bfloat16* __restrict__ Bl,
    const float* __restrict__ bias,
    __nv_bfloat16* __restrict__ Oh, __nv_bfloat16* __restrict__ Ol,
    float* __restrict__ Of, float* __restrict__ Of2, int N, int ld, int Klen)
{
    extern __shared__ char smem[];
    const uint32_t sb = smem_u32(smem);
    const int tid = threadIdx.x, lane = tid & 31, wid = tid >> 5;
    const int wm = wid & 1, wn = wid >> 1;
    const int bm = blockIdx.y << 7, bn = blockIdx.x << 7;

    if (MODE == 2) {
        size_t koff = (size_t)blockIdx.z * (size_t)Klen;
        Ah += koff; Al += koff; Bh += koff; Bl += koff;
        if (blockIdx.z) Of = Of2;
    }

    float acc[4][4][4];
    #pragma unroll
    for (int f = 0; f < 4; f++)
        #pragma unroll
        for (int g = 0; g < 4; g++)
            #pragma unroll
            for (int v = 0; v < 4; v++) acc[f][g][v] = 0.f;

    const int nc = Klen >> 6;
    stage_buf(Ah, Al, Bh, Bl, bm, bn, 0, ld, sb);
    CP_COMMIT();
    stage_buf(Ah, Al, Bh, Bl, bm, bn, 64, ld, sb + BUFB);
    CP_COMMIT();

    const int arow = wm * 64 + (lane & 15);
    const int acolb = ((lane >> 4) << 3) * 2;
    const int brow = wn * 32 + (lane & 7) + (((lane >> 4) & 1) << 3);
    const int bcolb = (((lane >> 3) & 1) << 3) * 2;

    for (int i = 0; i < nc; i++) {
        if (i < nc - 1) asm volatile("cp.async.wait_group 1;" ::: "memory");
        else           asm volatile("cp.async.wait_group 0;" ::: "memory");
        __syncthreads();

        const uint32_t base = sb + (uint32_t)(i & 1) * BUFB;
        #pragma unroll
        for (int kk = 0; kk < 4; kk++) {
            uint32_t Ahf[4][4], Alf[4][4], Bhf[2][4], Blf[2][4];
            const uint32_t ak = (uint32_t)(kk * 32) + acolb;
            const uint32_t bk = (uint32_t)(kk * 32) + bcolb;
            #pragma unroll
            for (int f = 0; f < 4; f++) {
                uint32_t ra = base + (uint32_t)((arow + f * 16) * ROWB) + ak;
                ldm_x4(Ahf[f], ra);
                ldm_x4(Alf[f], ra + TILEB);
            }
            #pragma unroll
            for (int p = 0; p < 2; p++) {
                uint32_t rb = base + 2u * TILEB + (uint32_t)((brow + p * 16) * ROWB) + bk;
                ldm_x4(Bhf[p], rb);
                ldm_x4(Blf[p], rb + TILEB);
            }
            #pragma unroll
            for (int f = 0; f < 4; f++)
                #pragma unroll
                for (int g = 0; g < 4; g++) {
                    const uint32_t* bh = &Bhf[g >> 1][(g & 1) << 1];
                    const uint32_t* bl = &Blf[g >> 1][(g & 1) << 1];
                    mma_bf16(acc[f][g], Ahf[f], bh);
                    mma_bf16(acc[f][g], Alf[f], bh);
                    mma_bf16(acc[f][g], Ahf[f], bl);
                }
        }

        if (i + 2 < nc) {
            __syncthreads();
            stage_buf(Ah, Al, Bh, Bl, bm, bn, (i + 2) << 6, ld, base);
            CP_COMMIT();
        }
    }

    // epilogue
    #pragma unroll
    for (int f = 0; f < 4; f++) {
        #pragma unroll
        for (int g = 0; g < 4; g++) {
            int r0 = bm + wm * 64 + f * 16 + (lane >> 2);
            int c0 = bn + wn * 32 + g * 8 + ((lane & 3) << 1);
            float bv0 = (MODE == 2) ? 0.f : bias[c0];
            float bv1 = (MODE == 2) ? 0.f : bias[c0 + 1];
            #pragma unroll
            for (int h = 0; h < 2; h++) {
                int r = r0 + h * 8;
                float v0 = acc[f][g][2 * h + 0] + bv0;
                float v1 = acc[f][g][2 * h + 1] + bv1;
                if (MODE == 0) {
                    v0 = fmaxf(v0, 0.f); v1 = fmaxf(v1, 0.f);
                    __nv_bfloat16 h0 = __float2bfloat16(v0), h1 = __float2bfloat16(v1);
                    __nv_bfloat16 l0 = __float2bfloat16(v0 - __bfloat162float(h0));
                    __nv_bfloat16 l1 = __float2bfloat16(v1 - __bfloat162float(h1));
                    ushort2 uh = make_ushort2(__bfloat16_as_ushort(h0), __bfloat16_as_ushort(h1));
                    ushort2 ul = make_ushort2(__bfloat16_as_ushort(l0), __bfloat16_as_ushort(l1));
                    *(ushort2*)(Oh + (size_t)r * N + c0) = uh;
                    *(ushort2*)(Ol + (size_t)r * N + c0) = ul;
                } else {
                    float2 o = make_float2(v0, v1);
                    *(float2*)(Of + (size_t)r * N + c0) = o;
                }
            }
        }
    }
}

// ---------------------------------------------------------------------------
// Launch
// ---------------------------------------------------------------------------
extern "C" void kernel_launch(void* const* d_in, const int* in_sizes, int n_in,
                              void* d_out, int out_size)
{
    const float* x  = (const float*)d_in[0];
    const float* W1 = (const float*)d_in[1];
    const float* b1 = (const float*)d_in[2];
    const float* W2 = (const float*)d_in[3];
    const float* b2 = (const float*)d_in[4];
    const float* W3 = (const float*)d_in[5];
    const float* b3 = (const float*)d_in[6];
    const float4* s0 = (const float4*)d_in[7];
    const float4* s1 = (const float4*)d_in[8];
    const float4* s2 = (const float4*)d_in[9];
    const float4* s3 = (const float4*)d_in[10];
    const float4* s4 = (const float4*)d_in[11];
    const float4* s5 = (const float4*)d_in[12];

    void* p;
    cudaGetSymbolAddress(&p, g_wh);  __nv_bfloat16* wh  = (__nv_bfloat16*)p;
    cudaGetSymbolAddress(&p, g_wl);  __nv_bfloat16* wl  = (__nv_bfloat16*)p;
    cudaGetSymbolAddress(&p, g_xh);  __nv_bfloat16* xh  = (__nv_bfloat16*)p;
    cudaGetSymbolAddress(&p, g_xl);  __nv_bfloat16* xl  = (__nv_bfloat16*)p;
    cudaGetSymbolAddress(&p, g_h1h); __nv_bfloat16* h1h = (__nv_bfloat16*)p;
    cudaGetSymbolAddress(&p, g_h1l); __nv_bfloat16* h1l = (__nv_bfloat16*)p;
    cudaGetSymbolAddress(&p, g_h2h); __nv_bfloat16* h2h = (__nv_bfloat16*)p;
    cudaGetSymbolAddress(&p, g_h2l); __nv_bfloat16* h2l = (__nv_bfloat16*)p;
    cudaGetSymbolAddress(&p, g_p0);  float* p0 = (float*)p;
    cudaGetSymbolAddress(&p, g_p1);  float* p1 = (float*)p;
    cudaGetSymbolAddress(&p, g_mb);  float* mb = (float*)p;

    cudaFuncSetAttribute(k_mgemm<0>, cudaFuncAttributeMaxDynamicSharedMemorySize, MG_SMEM);
    cudaFuncSetAttribute(k_mgemm<2>, cudaFuncAttributeMaxDynamicSharedMemorySize, MG_SMEM);

    // ---- selection: level-1 hist + scan, compact selected bin, finish ----
    k_zero<<<1, 256>>>();
    k_hist1<<<1024, 256>>>(s0, s1, s2, s3, s4, s5);
    k_scan1<<<1, 256>>>();
    k_compact<<<1024, 256>>>(s0, s1, s2, s3, s4, s5);
    k_finish<<<1, 1024>>>();

    // ---- x split ----
    k_split<<<1024, 256>>>((const float4*)x, xh, xl, 262144);

    // ---- layer 1 ----
    k_applyw<<<4096, 256>>>((const float4*)W1, s0, wh, wl, 1048576, 0u);
    k_applyb<<<4, 256>>>((const float4*)b1, s1, (float4*)mb, 1024, (unsigned)E0);
    k_mgemm<0><<<dim3(32, 8), 256, MG_SMEM>>>(xh, xl, wh, wl, mb, h1h, h1l, nullptr, nullptr, 4096, 1024, 1024);

    // ---- layer 2 ----
    k_applyw<<<16384, 256>>>((const float4*)W2, s2, wh, wl, 4194304, (unsigned)E1);
    k_applyb<<<4, 256>>>((const float4*)b2, s3, (float4*)mb, 1024, (unsigned)E2);
    k_mgemm<0><<<dim3(32, 8), 256, MG_SMEM>>>(h1h, h1l, wh, wl, mb, h2h, h2l, nullptr, nullptr, 4096, 4096, 4096);

    // ---- layer 3 (split-K=2 across blockIdx.z, then reduce with bias) ----
    k_applyw<<<4096, 256>>>((const float4*)W3, s4, wh, wl, 1048576, (unsigned)E3);
    k_applyb<<<1, 256>>>((const float4*)b3, s5, (float4*)mb, 256, (unsigned)E4);
    k_mgemm<2><<<dim3(8, 8, 2), 256, MG_SMEM>>>(h2h, h2l, wh, wl, mb, nullptr, nullptr, p0, p1, 1024, 4096, 2048);
    k_reduce3<<<1024, 256>>>((float4*)d_out, (const float4*)p0, (const float4*)p1, mb);
}

// round 8
// speedup vs baseline: 1.2383x; 1.1637x over previous
#include <cuda_runtime.h>
#include <cuda_bf16.h>
#include <cstdint>

// ---------------------------------------------------------------------------
// Problem constants (B=1024, D_IN=1024, D_H=4096, D_OUT=1024, SPARSITY=0.5)
// concat order: [sW1, sb1, sW2, sb2, sW3, sb3]
// n = 25175040, j = 12587520
// ---------------------------------------------------------------------------
#define NTOT   25175040
#define NTOT4  6293760
#define JRANK  12587520u

#define E0 4194304
#define E1 4198400
#define E2 20975616
#define E3 20979712
#define E4 25174016
#define F0 1048576
#define F1 1049600
#define F2 5243904
#define F3 5244928
#define F4 6293504

#define CAND_CAP (1<<20)

// ---------------------------------------------------------------------------
// Device scratch
// ---------------------------------------------------------------------------
__device__ __align__(256) __nv_bfloat16 g_wh[16777216];
__device__ __align__(256) __nv_bfloat16 g_wl[16777216];
__device__ __align__(256) __nv_bfloat16 g_xh[1048576],  g_xl[1048576];
__device__ __align__(256) __nv_bfloat16 g_h1h[4194304], g_h1l[4194304];
__device__ __align__(256) __nv_bfloat16 g_h2h[4194304], g_h2l[4194304];
__device__ __align__(256) float    g_p0[1048576], g_p1[1048576];   // layer3 split-K partials
__device__ __align__(256) float    g_mb[4096];
__device__ unsigned g_hist1[4096];
__device__ unsigned g_sel[16];   // 0:bin1 1:cum1 4:KT 8:tieth 9:candcnt
__device__ unsigned g_candk[CAND_CAP];
__device__ unsigned g_candi[CAND_CAP];

// ---------------------------------------------------------------------------
// PTX helpers (baseline ISA only: cp.async / ldmatrix / mma.sync)
// ---------------------------------------------------------------------------
__device__ __forceinline__ uint32_t smem_u32(const void* p) {
    uint32_t a;
    asm("{ .reg .u64 t; cvta.to.shared.u64 t, %1; cvt.u32.u64 %0, t; }" : "=r"(a) : "l"(p));
    return a;
}
__device__ __forceinline__ void cp16(uint32_t dst, const void* src) {
    asm volatile("cp.async.cg.shared.global [%0], [%1], 16;" :: "r"(dst), "l"(src));
}
#define CP_COMMIT() asm volatile("cp.async.commit_group;" ::: "memory")

__device__ __forceinline__ void ldm_x4(uint32_t* r, uint32_t addr) {
    asm volatile("ldmatrix.sync.aligned.m8n8.x4.shared.b16 {%0,%1,%2,%3}, [%4];"
        : "=r"(r[0]), "=r"(r[1]), "=r"(r[2]), "=r"(r[3]) : "r"(addr));
}
__device__ __forceinline__ void mma_bf16(float* c, const uint32_t* a, const uint32_t* b) {
    asm volatile(
        "mma.sync.aligned.m16n8k16.row.col.f32.bf16.bf16.f32 "
        "{%0,%1,%2,%3}, {%4,%5,%6,%7}, {%8,%9}, {%0,%1,%2,%3};"
        : "+f"(c[0]), "+f"(c[1]), "+f"(c[2]), "+f"(c[3])
        : "r"(a[0]), "r"(a[1]), "r"(a[2]), "r"(a[3]), "r"(b[0]), "r"(b[1]));
}

// ---------------------------------------------------------------------------
// Selection
// ---------------------------------------------------------------------------
__device__ __forceinline__ unsigned f2key(float f) {
    unsigned u = __float_as_uint(f);
    return (u & 0x80000000u) ? ~u : (u | 0x80000000u);
}
__device__ __forceinline__ float4 fetch4(int i4,
    const float4* __restrict__ s0, const float4* __restrict__ s1,
    const float4* __restrict__ s2, const float4* __restrict__ s3,
    const float4* __restrict__ s4, const float4* __restrict__ s5)
{
    if (i4 < F0) return s0[i4];
    if (i4 < F1) return s1[i4 - F0];
    if (i4 < F2) return s2[i4 - F1];
    if (i4 < F3) return s3[i4 - F2];
    if (i4 < F4) return s4[i4 - F3];
    return s5[i4 - F4];
}

__global__ void k_zero() {
    int t = threadIdx.x;
    for (int i = t; i < 4096; i += 256) g_hist1[i] = 0;
    if (t < 16) g_sel[t] = 0;
}

__global__ void k_hist1(
    const float4* __restrict__ s0, const float4* __restrict__ s1,
    const float4* __restrict__ s2, const float4* __restrict__ s3,
    const float4* __restrict__ s4, const float4* __restrict__ s5)
{
    __shared__ unsigned h[4096];
    for (int i = threadIdx.x; i < 4096; i += blockDim.x) h[i] = 0;
    __syncthreads();
    const int stride = gridDim.x * blockDim.x;
    for (int i4 = blockIdx.x * blockDim.x + threadIdx.x; i4 < NTOT4; i4 += stride) {
        float4 v = fetch4(i4, s0, s1, s2, s3, s4, s5);
        atomicAdd(&h[f2key(v.x) >> 20], 1u);
        atomicAdd(&h[f2key(v.y) >> 20], 1u);
        atomicAdd(&h[f2key(v.z) >> 20], 1u);
        atomicAdd(&h[f2key(v.w) >> 20], 1u);
    }
    __syncthreads();
    for (int i = threadIdx.x; i < 4096; i += blockDim.x) {
        unsigned c = h[i];
        if (c) atomicAdd(&g_hist1[i], c);
    }
}

__global__ void k_scan1() {
    __shared__ unsigned part[256];
    int t = threadIdx.x;
    unsigned s = 0;
    for (int i = 0; i < 16; i++) s += g_hist1[t * 16 + i];
    part[t] = s;
    __syncthreads();
    if (t == 0) {
        unsigned c = 0;
        int ch = 0;
        for (; ch < 255; ch++) { if (c + part[ch] > JRANK) break; c += part[ch]; }
        int b = ch * 16;
        for (;; b++) { unsigned hh = g_hist1[b]; if (c + hh > JRANK) break; c += hh; }
        g_sel[0] = (unsigned)b; g_sel[1] = c;
    }
}

__global__ void k_compact(
    const float4* __restrict__ s0, const float4* __restrict__ s1,
    const float4* __restrict__ s2, const float4* __restrict__ s3,
    const float4* __restrict__ s4, const float4* __restrict__ s5)
{
    const unsigned bin = g_sel[0];
    const int stride = gridDim.x * blockDim.x;
    for (int i4 = blockIdx.x * blockDim.x + threadIdx.x; i4 < NTOT4; i4 += stride) {
        float4 v = fetch4(i4, s0, s1, s2, s3, s4, s5);
        float vv[4] = {v.x, v.y, v.z, v.w};
        #pragma unroll
        for (int c = 0; c < 4; c++) {
            unsigned key = f2key(vv[c]);
            if ((key >> 20) == bin) {
                unsigned p = atomicAdd(&g_sel[9], 1u);
                if (p < CAND_CAP) { g_candk[p] = key; g_candi[p] = (unsigned)(i4 * 4 + c); }
            }
        }
    }
}

__global__ void k_finish() {
    __shared__ unsigned h[1024];
    __shared__ unsigned ties[2048];
    __shared__ unsigned sh_b2, sh_c2, sh_KT, sh_need, sh_tc;
    int t = threadIdx.x;
    unsigned cnt = g_sel[9]; if (cnt > CAND_CAP) cnt = CAND_CAP;

    h[t] = 0;
    if (t == 0) sh_tc = 0;
    __syncthreads();
    for (unsigned j = t; j < cnt; j += 1024) atomicAdd(&h[(g_candk[j] >> 10) & 1023u], 1u);
    __syncthreads();
    if (t == 0) {
        unsigned c = g_sel[1];
        int b = 0;
        for (;; b++) { if (c + h[b] > JRANK) break; c += h[b]; }
        sh_b2 = (unsigned)b; sh_c2 = c;
    }
    __syncthreads();
    unsigned b2 = sh_b2;
    h[t] = 0;
    __syncthreads();
    for (unsigned j = t; j < cnt; j += 1024) {
        unsigned k = g_candk[j];
        if (((k >> 10) & 1023u) == b2) atomicAdd(&h[k & 1023u], 1u);
    }
    __syncthreads();
    if (t == 0) {
        unsigned c = sh_c2;
        int b = 0;
        for (;; b++) { if (c + h[b] > JRANK) break; c += h[b]; }
        sh_KT = (g_sel[0] << 20) | (b2 << 10) | (unsigned)b;
        sh_need = JRANK - c;
    }
    __syncthreads();
    unsigned KT = sh_KT;
    for (unsigned j = t; j < cnt; j += 1024) {
        if (g_candk[j] == KT) {
            unsigned p = atomicAdd(&sh_tc, 1u);
            if (p < 2048) ties[p] = g_candi[j];
        }
    }
    __syncthreads();
    if (t == 0) {
        int n = (int)sh_tc; if (n > 2048) n = 2048;
        for (int i = 1; i < n; i++) {
            unsigned v = ties[i]; int j = i - 1;
            while (j >= 0 && ties[j] > v) { ties[j + 1] = ties[j]; j--; }
            ties[j + 1] = v;
        }
        g_sel[4] = KT;
        g_sel[8] = (sh_need < (unsigned)n) ? ties[sh_need] : 0xFFFFFFFFu;
    }
}

// ---------------------------------------------------------------------------
// Apply / split
// ---------------------------------------------------------------------------
__global__ void k_applyw(const float4* __restrict__ w, const float4* __restrict__ s,
                         __nv_bfloat16* __restrict__ oh, __nv_bfloat16* __restrict__ ol,
                         int n4, unsigned flatoff)
{
    const unsigned KT = g_sel[4], tieth = g_sel[8];
    int i = blockIdx.x * blockDim.x + threadIdx.x;
    if (i >= n4) return;
    float4 wv = w[i], sv = s[i];
    float sa[4] = {sv.x, sv.y, sv.z, sv.w};
    float wa[4] = {wv.x, wv.y, wv.z, wv.w};
    unsigned fb = flatoff + 4u * (unsigned)i;
    ushort4 uh, ul;
    unsigned short* ph = (unsigned short*)&uh;
    unsigned short* pl = (unsigned short*)&ul;
    #pragma unroll
    for (int c = 0; c < 4; c++) {
        unsigned key = f2key(sa[c]);
        bool keep = (key > KT) || (key == KT && (fb + c) >= tieth);
        float v = keep ? wa[c] : 0.f;
        __nv_bfloat16 hi = __float2bfloat16(v);
        __nv_bfloat16 lo = __float2bfloat16(v - __bfloat162float(hi));
        ph[c] = __bfloat16_as_ushort(hi);
        pl[c] = __bfloat16_as_ushort(lo);
    }
    *(ushort4*)(oh + 4 * (size_t)i) = uh;
    *(ushort4*)(ol + 4 * (size_t)i) = ul;
}

__global__ void k_applyb(const float4* __restrict__ w, const float4* __restrict__ s,
                         float4* __restrict__ dst, int n4, unsigned flatoff)
{
    const unsigned KT = g_sel[4], tieth = g_sel[8];
    int i = blockIdx.x * blockDim.x + threadIdx.x;
    if (i >= n4) return;
    float4 wv = w[i], sv = s[i];
    float sa[4] = {sv.x, sv.y, sv.z, sv.w};
    float wa[4] = {wv.x, wv.y, wv.z, wv.w};
    unsigned fb = flatoff + 4u * (unsigned)i;
    #pragma unroll
    for (int c = 0; c < 4; c++) {
        unsigned key = f2key(sa[c]);
        bool keep = (key > KT) || (key == KT && (fb + c) >= tieth);
        if (!keep) wa[c] = 0.f;
    }
    dst[i] = make_float4(wa[0], wa[1], wa[2], wa[3]);
}

__global__ void k_split(const float4* __restrict__ x,
                        __nv_bfloat16* __restrict__ oh, __nv_bfloat16* __restrict__ ol, int n4)
{
    int i = blockIdx.x * blockDim.x + threadIdx.x;
    if (i >= n4) return;
    float4 v = x[i];
    float va[4] = {v.x, v.y, v.z, v.w};
    ushort4 uh, ul;
    unsigned short* ph = (unsigned short*)&uh;
    unsigned short* pl = (unsigned short*)&ul;
    #pragma unroll
    for (int c = 0; c < 4; c++) {
        __nv_bfloat16 hi = __float2bfloat16(va[c]);
        __nv_bfloat16 lo = __float2bfloat16(va[c] - __bfloat162float(hi));
        ph[c] = __bfloat16_as_ushort(hi);
        pl[c] = __bfloat16_as_ushort(lo);
    }
    *(ushort4*)(oh + 4 * (size_t)i) = uh;
    *(ushort4*)(ol + 4 * (size_t)i) = ul;
}

// layer3 reduce: out = p0 + p1 + bias
__global__ void k_reduce3(float4* __restrict__ out, const float4* __restrict__ p0,
                          const float4* __restrict__ p1, const float* __restrict__ bias)
{
    int i = blockIdx.x * blockDim.x + threadIdx.x;   // of 262144 float4s, N=1024
    float4 a = p0[i], b = p1[i];
    int c0 = (i << 2) & 1023;
    float4 o;
    o.x = a.x + b.x + bias[c0];
    o.y = a.y + b.y + bias[c0 + 1];
    o.z = a.z + b.z + bias[c0 + 2];
    o.w = a.w + b.w + bias[c0 + 3];
    out[i] = o;
}

// ---------------------------------------------------------------------------
// mma.sync bf16 split GEMM: C[M,N] = A[M,K]*B[N,K]^T + bias
//   C ~= Ahi*Bhi + Alo*Bhi + Ahi*Blo   (fp32 accumulate)
// CTA tile 128x128, BK=64, 256 threads (8 warps, 2m x 4n, warp tile 64x32)
// Row-padded SMEM (144B stride), 3-stage cp.async pipeline (single sync/chunk):
//   wait_group 1 -> sync -> prefetch chunk i+2 -> compute chunk i
// MODE 0: relu + bf16 hi/lo outputs; MODE 2: split-K fp32 partial (blockIdx.z half).
// ---------------------------------------------------------------------------
#define ROWB    144
#define TILEB   18432          // 128 * 144
#define BUFB    73728          // 4 tiles
#define MG_SMEM 221184         // 3 buffers (216 KB)

__device__ __forceinline__ void stage_tile(const __nv_bfloat16* __restrict__ g,
                                           int row0, int k0, int ld, uint32_t sdst)
{
    int tid = threadIdx.x;
    // 128 rows x 64 bf16 = 128 rows x 8 chunks of 16B = 1024 cp.async ops
    #pragma unroll
    for (int i = 0; i < 4; i++) {
        int s = tid + (i << 8);
        int r = s >> 3, sub = s & 7;
        cp16(sdst + (uint32_t)(r * ROWB + sub * 16),
             g + (size_t)(row0 + r) * ld + k0 + sub * 8);
    }
}

__device__ __forceinline__ void stage_buf(
    const __nv_bfloat16* Ah, const __nv_bfloat16* Al,
    const __nv_bfloat16* Bh, const __nv_bfloat16* Bl,
    int bm, int bn, int k0, int ld, uint32_t sbase)
{
    stage_tile(Ah, bm, k0, ld, sbase);
    stage_tile(Al, bm, k0, ld, sbase + TILEB);
    stage_tile(Bh, bn, k0, ld, sbase + 2 * TILEB);
    stage_tile(Bl, bn, k0, ld, sbase + 3 * TILEB);
}

template<int MODE>
__global__ void __launch_bounds__(256, 1) k_mgemm(
    const __nv_bfloat16* __restrict__ Ah, const __nv_bfloat16* __restrict__ Al,
    const __nv_bfloat16* __restrict__ Bh, const __nv_bfloat16* __restrict__ Bl,
    const float* __restrict__ bias,
    __nv_bfloat16* __restrict__ Oh, __nv_bfloat16* __restrict__ Ol,
    float* __restrict__ Of, float* __restrict__ Of2, int N, int ld, int Klen)
{
    extern __shared__ char smem[];
    const uint32_t sb = smem_u32(smem);
    const int tid = threadIdx.x, lane = tid & 31, wid = tid >> 5;
    const int wm = wid & 1, wn = wid >> 1;
    const int bm = blockIdx.y << 7, bn = blockIdx.x << 7;

    if (MODE == 2) {
        size_t koff = (size_t)blockIdx.z * (size_t)Klen;
        Ah += koff; Al += koff; Bh += koff; Bl += koff;
        if (blockIdx.z) Of = Of2;
    }

    float acc[4][4][4];
    #pragma unroll
    for (int f = 0; f < 4; f++)
        #pragma unroll
        for (int g = 0; g < 4; g++)
            #pragma unroll
            for (int v = 0; v < 4; v++) acc[f][g][v] = 0.f;

    const int nc = Klen >> 6;
    stage_buf(Ah, Al, Bh, Bl, bm, bn, 0, ld, sb);
    CP_COMMIT();
    stage_buf(Ah, Al, Bh, Bl, bm, bn, 64, ld, sb + BUFB);
    CP_COMMIT();

    const int arow = wm * 64 + (lane & 15);
    const int acolb = ((lane >> 4) << 3) * 2;
    const int brow = wn * 32 + (lane & 7) + (((lane >> 4) & 1) << 3);
    const int bcolb = (((lane >> 3) & 1) << 3) * 2;

    for (int i = 0; i < nc; i++) {
        if (i < nc - 1) asm volatile("cp.async.wait_group 1;" ::: "memory");
        else           asm volatile("cp.async.wait_group 0;" ::: "memory");
        __syncthreads();

        // prefetch chunk i+2 into the buffer last read at chunk i-1 (safe: sync above)
        if (i + 2 < nc) {
            uint32_t sd = sb + (uint32_t)((i + 2) % 3) * BUFB;
            stage_buf(Ah, Al, Bh, Bl, bm, bn, (i + 2) << 6, ld, sd);
            CP_COMMIT();
        }

        const uint32_t base = sb + (uint32_t)(i % 3) * BUFB;
        #pragma unroll
        for (int kk = 0; kk < 4; kk++) {
            uint32_t Ahf[4][4], Alf[4][4], Bhf[2][4], Blf[2][4];
            const uint32_t ak = (uint32_t)(kk * 32) + acolb;
            const uint32_t bk = (uint32_t)(kk * 32) + bcolb;
            #pragma unroll
            for (int f = 0; f < 4; f++) {
                uint32_t ra = base + (uint32_t)((arow + f * 16) * ROWB) + ak;
                ldm_x4(Ahf[f], ra);
                ldm_x4(Alf[f], ra + TILEB);
            }
            #pragma unroll
            for (int p = 0; p < 2; p++) {
                uint32_t rb = base + 2u * TILEB + (uint32_t)((brow + p * 16) * ROWB) + bk;
                ldm_x4(Bhf[p], rb);
                ldm_x4(Blf[p], rb + TILEB);
            }
            #pragma unroll
            for (int f = 0; f < 4; f++)
                #pragma unroll
                for (int g = 0; g < 4; g++) {
                    const uint32_t* bh = &Bhf[g >> 1][(g & 1) << 1];
                    const uint32_t* bl = &Blf[g >> 1][(g & 1) << 1];
                    mma_bf16(acc[f][g], Ahf[f], bh);
                    mma_bf16(acc[f][g], Alf[f], bh);
                    mma_bf16(acc[f][g], Ahf[f], bl);
                }
        }
    }

    // epilogue
    #pragma unroll
    for (int f = 0; f < 4; f++) {
        #pragma unroll
        for (int g = 0; g < 4; g++) {
            int r0 = bm + wm * 64 + f * 16 + (lane >> 2);
            int c0 = bn + wn * 32 + g * 8 + ((lane & 3) << 1);
            float bv0 = (MODE == 2) ? 0.f : bias[c0];
            float bv1 = (MODE == 2) ? 0.f : bias[c0 + 1];
            #pragma unroll
            for (int h = 0; h < 2; h++) {
                int r = r0 + h * 8;
                float v0 = acc[f][g][2 * h + 0] + bv0;
                float v1 = acc[f][g][2 * h + 1] + bv1;
                if (MODE == 0) {
                    v0 = fmaxf(v0, 0.f); v1 = fmaxf(v1, 0.f);
                    __nv_bfloat16 h0 = __float2bfloat16(v0), h1 = __float2bfloat16(v1);
                    __nv_bfloat16 l0 = __float2bfloat16(v0 - __bfloat162float(h0));
                    __nv_bfloat16 l1 = __float2bfloat16(v1 - __bfloat162float(h1));
                    ushort2 uh = make_ushort2(__bfloat16_as_ushort(h0), __bfloat16_as_ushort(h1));
                    ushort2 ul = make_ushort2(__bfloat16_as_ushort(l0), __bfloat16_as_ushort(l1));
                    *(ushort2*)(Oh + (size_t)r * N + c0) = uh;
                    *(ushort2*)(Ol + (size_t)r * N + c0) = ul;
                } else {
                    float2 o = make_float2(v0, v1);
                    *(float2*)(Of + (size_t)r * N + c0) = o;
                }
            }
        }
    }
}

// ---------------------------------------------------------------------------
// Launch
// ---------------------------------------------------------------------------
extern "C" void kernel_launch(void* const* d_in, const int* in_sizes, int n_in,
                              void* d_out, int out_size)
{
    const float* x  = (const float*)d_in[0];
    const float* W1 = (const float*)d_in[1];
    const float* b1 = (const float*)d_in[2];
    const float* W2 = (const float*)d_in[3];
    const float* b2 = (const float*)d_in[4];
    const float* W3 = (const float*)d_in[5];
    const float* b3 = (const float*)d_in[6];
    const float4* s0 = (const float4*)d_in[7];
    const float4* s1 = (const float4*)d_in[8];
    const float4* s2 = (const float4*)d_in[9];
    const float4* s3 = (const float4*)d_in[10];
    const float4* s4 = (const float4*)d_in[11];
    const float4* s5 = (const float4*)d_in[12];

    void* p;
    cudaGetSymbolAddress(&p, g_wh);  __nv_bfloat16* wh  = (__nv_bfloat16*)p;
    cudaGetSymbolAddress(&p, g_wl);  __nv_bfloat16* wl  = (__nv_bfloat16*)p;
    cudaGetSymbolAddress(&p, g_xh);  __nv_bfloat16* xh  = (__nv_bfloat16*)p;
    cudaGetSymbolAddress(&p, g_xl);  __nv_bfloat16* xl  = (__nv_bfloat16*)p;
    cudaGetSymbolAddress(&p, g_h1h); __nv_bfloat16* h1h = (__nv_bfloat16*)p;
    cudaGetSymbolAddress(&p, g_h1l); __nv_bfloat16* h1l = (__nv_bfloat16*)p;
    cudaGetSymbolAddress(&p, g_h2h); __nv_bfloat16* h2h = (__nv_bfloat16*)p;
    cudaGetSymbolAddress(&p, g_h2l); __nv_bfloat16* h2l = (__nv_bfloat16*)p;
    cudaGetSymbolAddress(&p, g_p0);  float* p0 = (float*)p;
    cudaGetSymbolAddress(&p, g_p1);  float* p1 = (float*)p;
    cudaGetSymbolAddress(&p, g_mb);  float* mb = (float*)p;

    cudaFuncSetAttribute(k_mgemm<0>, cudaFuncAttributeMaxDynamicSharedMemorySize, MG_SMEM);
    cudaFuncSetAttribute(k_mgemm<2>, cudaFuncAttributeMaxDynamicSharedMemorySize, MG_SMEM);

    // ---- selection: level-1 hist + scan, compact selected bin, finish ----
    k_zero<<<1, 256>>>();
    k_hist1<<<1024, 256>>>(s0, s1, s2, s3, s4, s5);
    k_scan1<<<1, 256>>>();
    k_compact<<<1024, 256>>>(s0, s1, s2, s3, s4, s5);
    k_finish<<<1, 1024>>>();

    // ---- x split ----
    k_split<<<1024, 256>>>((const float4*)x, xh, xl, 262144);

    // ---- layer 1 ----
    k_applyw<<<4096, 256>>>((const float4*)W1, s0, wh, wl, 1048576, 0u);
    k_applyb<<<4, 256>>>((const float4*)b1, s1, (float4*)mb, 1024, (unsigned)E0);
    k_mgemm<0><<<dim3(32, 8), 256, MG_SMEM>>>(xh, xl, wh, wl, mb, h1h, h1l, nullptr, nullptr, 4096, 1024, 1024);

    // ---- layer 2 ----
    k_applyw<<<16384, 256>>>((const float4*)W2, s2, wh, wl, 4194304, (unsigned)E1);
    k_applyb<<<4, 256>>>((const float4*)b2, s3, (float4*)mb, 1024, (unsigned)E2);
    k_mgemm<0><<<dim3(32, 8), 256, MG_SMEM>>>(h1h, h1l, wh, wl, mb, h2h, h2l, nullptr, nullptr, 4096, 4096, 4096);

    // ---- layer 3 (split-K=2 across blockIdx.z, then reduce with bias) ----
    k_applyw<<<4096, 256>>>((const float4*)W3, s4, wh, wl, 1048576, (unsigned)E3);
    k_applyb<<<1, 256>>>((const float4*)b3, s5, (float4*)mb, 256, (unsigned)E4);
    k_mgemm<2><<<dim3(8, 8, 2), 256, MG_SMEM>>>(h2h, h2l, wh, wl, mb, nullptr, nullptr, p0, p1, 1024, 4096, 2048);
    k_reduce3<<<1024, 256>>>((float4*)d_out, (const float4*)p0, (const float4*)p1, mb);
}

// round 9
// speedup vs baseline: 1.2595x; 1.0172x over previous
#include <cuda_runtime.h>
#include <cuda_bf16.h>
#include <cstdint>

// ---------------------------------------------------------------------------
// Problem constants (B=1024, D_IN=1024, D_H=4096, D_OUT=1024, SPARSITY=0.5)
// concat order: [sW1, sb1, sW2, sb2, sW3, sb3]
// n = 25175040, j = 12587520
// ---------------------------------------------------------------------------
#define NTOT   25175040
#define NTOT4  6293760
#define JRANK  12587520u

#define E0 4194304
#define E1 4198400
#define E2 20975616
#define E3 20979712
#define E4 25174016
#define F0 1048576
#define F1 1049600
#define F2 5243904
#define F3 5244928
#define F4 6293504

#define CAND_CAP (1<<20)

// ---------------------------------------------------------------------------
// Device scratch
// ---------------------------------------------------------------------------
__device__ __align__(256) __nv_bfloat16 g_wh[16777216];
__device__ __align__(256) __nv_bfloat16 g_wl[16777216];
__device__ __align__(256) __nv_bfloat16 g_xh[1048576],  g_xl[1048576];
__device__ __align__(256) __nv_bfloat16 g_h1h[4194304], g_h1l[4194304];
__device__ __align__(256) __nv_bfloat16 g_h2h[4194304], g_h2l[4194304];
__device__ __align__(256) float    g_p0[1048576], g_p1[1048576];   // layer3 split-K partials
__device__ __align__(256) float    g_mb[4096];
__device__ unsigned g_hist1[4096];
__device__ unsigned g_sel[16];   // 0:bin1 1:cum1 4:KT 8:tieth 9:candcnt
__device__ unsigned g_candk[CAND_CAP];
__device__ unsigned g_candi[CAND_CAP];

// ---------------------------------------------------------------------------
// PTX helpers (baseline ISA only: cp.async / ldmatrix / mma.sync)
// ---------------------------------------------------------------------------
__device__ __forceinline__ uint32_t smem_u32(const void* p) {
    uint32_t a;
    asm("{ .reg .u64 t; cvta.to.shared.u64 t, %1; cvt.u32.u64 %0, t; }" : "=r"(a) : "l"(p));
    return a;
}
__device__ __forceinline__ void cp16(uint32_t dst, const void* src) {
    asm volatile("cp.async.cg.shared.global [%0], [%1], 16;" :: "r"(dst), "l"(src));
}
#define CP_COMMIT() asm volatile("cp.async.commit_group;" ::: "memory")

__device__ __forceinline__ void ldm_x4(uint32_t* r, uint32_t addr) {
    asm volatile("ldmatrix.sync.aligned.m8n8.x4.shared.b16 {%0,%1,%2,%3}, [%4];"
        : "=r"(r[0]), "=r"(r[1]), "=r"(r[2]), "=r"(r[3]) : "r"(addr));
}
__device__ __forceinline__ void mma_bf16(float* c, const uint32_t* a, const uint32_t* b) {
    asm volatile(
        "mma.sync.aligned.m16n8k16.row.col.f32.bf16.bf16.f32 "
        "{%0,%1,%2,%3}, {%4,%5,%6,%7}, {%8,%9}, {%0,%1,%2,%3};"
        : "+f"(c[0]), "+f"(c[1]), "+f"(c[2]), "+f"(c[3])
        : "r"(a[0]), "r"(a[1]), "r"(a[2]), "r"(a[3]), "r"(b[0]), "r"(b[1]));
}

// ---------------------------------------------------------------------------
// Selection
// ---------------------------------------------------------------------------
__device__ __forceinline__ unsigned f2key(float f) {
    unsigned u = __float_as_uint(f);
    return (u & 0x80000000u) ? ~u : (u | 0x80000000u);
}
__device__ __forceinline__ float4 fetch4(int i4,
    const float4* __restrict__ s0, const float4* __restrict__ s1,
    const float4* __restrict__ s2, const float4* __restrict__ s3,
    const float4* __restrict__ s4, const float4* __restrict__ s5)
{
    if (i4 < F0) return s0[i4];
    if (i4 < F1) return s1[i4 - F0];
    if (i4 < F2) return s2[i4 - F1];
    if (i4 < F3) return s3[i4 - F2];
    if (i4 < F4) return s4[i4 - F3];
    return s5[i4 - F4];
}

__global__ void k_zero() {
    int t = threadIdx.x;
    for (int i = t; i < 4096; i += 256) g_hist1[i] = 0;
    if (t < 16) g_sel[t] = 0;
}

// 2 float4 per thread per iteration (MLP=2)
__global__ void k_hist1(
    const float4* __restrict__ s0, const float4* __restrict__ s1,
    const float4* __restrict__ s2, const float4* __restrict__ s3,
    const float4* __restrict__ s4, const float4* __restrict__ s5)
{
    __shared__ unsigned h[4096];
    for (int i = threadIdx.x; i < 4096; i += blockDim.x) h[i] = 0;
    __syncthreads();
    const int stride = gridDim.x * blockDim.x;          // in pair units
    const int npair = NTOT4 >> 1;
    for (int ip = blockIdx.x * blockDim.x + threadIdx.x; ip < npair; ip += stride) {
        int j = ip << 1;
        float4 v0 = fetch4(j, s0, s1, s2, s3, s4, s5);
        float4 v1 = fetch4(j + 1, s0, s1, s2, s3, s4, s5);
        atomicAdd(&h[f2key(v0.x) >> 20], 1u);
        atomicAdd(&h[f2key(v0.y) >> 20], 1u);
        atomicAdd(&h[f2key(v0.z) >> 20], 1u);
        atomicAdd(&h[f2key(v0.w) >> 20], 1u);
        atomicAdd(&h[f2key(v1.x) >> 20], 1u);
        atomicAdd(&h[f2key(v1.y) >> 20], 1u);
        atomicAdd(&h[f2key(v1.z) >> 20], 1u);
        atomicAdd(&h[f2key(v1.w) >> 20], 1u);
    }
    __syncthreads();
    for (int i = threadIdx.x; i < 4096; i += blockDim.x) {
        unsigned c = h[i];
        if (c) atomicAdd(&g_hist1[i], c);
    }
}

__global__ void k_scan1() {
    __shared__ unsigned part[256];
    int t = threadIdx.x;
    unsigned s = 0;
    for (int i = 0; i < 16; i++) s += g_hist1[t * 16 + i];
    part[t] = s;
    __syncthreads();
    if (t == 0) {
        unsigned c = 0;
        int ch = 0;
        for (; ch < 255; ch++) { if (c + part[ch] > JRANK) break; c += part[ch]; }
        int b = ch * 16;
        for (;; b++) { unsigned hh = g_hist1[b]; if (c + hh > JRANK) break; c += hh; }
        g_sel[0] = (unsigned)b; g_sel[1] = c;
    }
}

__global__ void k_compact(
    const float4* __restrict__ s0, const float4* __restrict__ s1,
    const float4* __restrict__ s2, const float4* __restrict__ s3,
    const float4* __restrict__ s4, const float4* __restrict__ s5)
{
    const unsigned bin = g_sel[0];
    const int stride = gridDim.x * blockDim.x;
    const int npair = NTOT4 >> 1;
    for (int ip = blockIdx.x * blockDim.x + threadIdx.x; ip < npair; ip += stride) {
        int j = ip << 1;
        float4 v0 = fetch4(j, s0, s1, s2, s3, s4, s5);
        float4 v1 = fetch4(j + 1, s0, s1, s2, s3, s4, s5);
        float vv[8] = {v0.x, v0.y, v0.z, v0.w, v1.x, v1.y, v1.z, v1.w};
        #pragma unroll
        for (int c = 0; c < 8; c++) {
            unsigned key = f2key(vv[c]);
            if ((key >> 20) == bin) {
                unsigned p = atomicAdd(&g_sel[9], 1u);
                if (p < CAND_CAP) { g_candk[p] = key; g_candi[p] = (unsigned)(j * 4 + c); }
            }
        }
    }
}

__global__ void k_finish() {
    __shared__ unsigned h[1024];
    __shared__ unsigned ties[2048];
    __shared__ unsigned sh_b2, sh_c2, sh_KT, sh_need, sh_tc;
    int t = threadIdx.x;
    unsigned cnt = g_sel[9]; if (cnt > CAND_CAP) cnt = CAND_CAP;

    h[t] = 0;
    if (t == 0) sh_tc = 0;
    __syncthreads();
    for (unsigned j = t; j < cnt; j += 1024) atomicAdd(&h[(g_candk[j] >> 10) & 1023u], 1u);
    __syncthreads();
    if (t == 0) {
        unsigned c = g_sel[1];
        int b = 0;
        for (;; b++) { if (c + h[b] > JRANK) break; c += h[b]; }
        sh_b2 = (unsigned)b; sh_c2 = c;
    }
    __syncthreads();
    unsigned b2 = sh_b2;
    h[t] = 0;
    __syncthreads();
    for (unsigned j = t; j < cnt; j += 1024) {
        unsigned k = g_candk[j];
        if (((k >> 10) & 1023u) == b2) atomicAdd(&h[k & 1023u], 1u);
    }
    __syncthreads();
    if (t == 0) {
        unsigned c = sh_c2;
        int b = 0;
        for (;; b++) { if (c + h[b] > JRANK) break; c += h[b]; }
        sh_KT = (g_sel[0] << 20) | (b2 << 10) | (unsigned)b;
        sh_need = JRANK - c;
    }
    __syncthreads();
    unsigned KT = sh_KT;
    for (unsigned j = t; j < cnt; j += 1024) {
        if (g_candk[j] == KT) {
            unsigned p = atomicAdd(&sh_tc, 1u);
            if (p < 2048) ties[p] = g_candi[j];
        }
    }
    __syncthreads();
    if (t == 0) {
        int n = (int)sh_tc; if (n > 2048) n = 2048;
        for (int i = 1; i < n; i++) {
            unsigned v = ties[i]; int j = i - 1;
            while (j >= 0 && ties[j] > v) { ties[j + 1] = ties[j]; j--; }
            ties[j + 1] = v;
        }
        g_sel[4] = KT;
        g_sel[8] = (sh_need < (unsigned)n) ? ties[sh_need] : 0xFFFFFFFFu;
    }
}

// ---------------------------------------------------------------------------
// Apply / split (2 float4 = 32B per thread)
// ---------------------------------------------------------------------------
__global__ void k_applyw(const float4* __restrict__ w, const float4* __restrict__ s,
                         __nv_bfloat16* __restrict__ oh, __nv_bfloat16* __restrict__ ol,
                         int npair, unsigned flatoff)
{
    const unsigned KT = g_sel[4], tieth = g_sel[8];
    int ip = blockIdx.x * blockDim.x + threadIdx.x;
    if (ip >= npair) return;
    int i = ip << 1;
    float4 wv0 = w[i], wv1 = w[i + 1], sv0 = s[i], sv1 = s[i + 1];
    float sa[8] = {sv0.x, sv0.y, sv0.z, sv0.w, sv1.x, sv1.y, sv1.z, sv1.w};
    float wa[8] = {wv0.x, wv0.y, wv0.z, wv0.w, wv1.x, wv1.y, wv1.z, wv1.w};
    unsigned fb = flatoff + 4u * (unsigned)i;
    unsigned short ph[8], pl[8];
    #pragma unroll
    for (int c = 0; c < 8; c++) {
        unsigned key = f2key(sa[c]);
        bool keep = (key > KT) || (key == KT && (fb + c) >= tieth);
        float v = keep ? wa[c] : 0.f;
        __nv_bfloat16 hi = __float2bfloat16(v);
        __nv_bfloat16 lo = __float2bfloat16(v - __bfloat162float(hi));
        ph[c] = __bfloat16_as_ushort(hi);
        pl[c] = __bfloat16_as_ushort(lo);
    }
    *(uint4*)(oh + 8 * (size_t)ip) = *(uint4*)ph;
    *(uint4*)(ol + 8 * (size_t)ip) = *(uint4*)pl;
}

__global__ void k_applyb(const float4* __restrict__ w, const float4* __restrict__ s,
                         float4* __restrict__ dst, int n4, unsigned flatoff)
{
    const unsigned KT = g_sel[4], tieth = g_sel[8];
    int i = blockIdx.x * blockDim.x + threadIdx.x;
    if (i >= n4) return;
    float4 wv = w[i], sv = s[i];
    float sa[4] = {sv.x, sv.y, sv.z, sv.w};
    float wa[4] = {wv.x, wv.y, wv.z, wv.w};
    unsigned fb = flatoff + 4u * (unsigned)i;
    #pragma unroll
    for (int c = 0; c < 4; c++) {
        unsigned key = f2key(sa[c]);
        bool keep = (key > KT) || (key == KT && (fb + c) >= tieth);
        if (!keep) wa[c] = 0.f;
    }
    dst[i] = make_float4(wa[0], wa[1], wa[2], wa[3]);
}

__global__ void k_split(const float4* __restrict__ x,
                        __nv_bfloat16* __restrict__ oh, __nv_bfloat16* __restrict__ ol, int npair)
{
    int ip = blockIdx.x * blockDim.x + threadIdx.x;
    if (ip >= npair) return;
    int i = ip << 1;
    float4 v0 = x[i], v1 = x[i + 1];
    float va[8] = {v0.x, v0.y, v0.z, v0.w, v1.x, v1.y, v1.z, v1.w};
    unsigned short ph[8], pl[8];
    #pragma unroll
    for (int c = 0; c < 8; c++) {
        __nv_bfloat16 hi = __float2bfloat16(va[c]);
        __nv_bfloat16 lo = __float2bfloat16(va[c] - __bfloat162float(hi));
        ph[c] = __bfloat16_as_ushort(hi);
        pl[c] = __bfloat16_as_ushort(lo);
    }
    *(uint4*)(oh + 8 * (size_t)ip) = *(uint4*)ph;
    *(uint4*)(ol + 8 * (size_t)ip) = *(uint4*)pl;
}

// layer3 reduce: out = p0 + p1 + bias
__global__ void k_reduce3(float4* __restrict__ out, const float4* __restrict__ p0,
                          const float4* __restrict__ p1, const float* __restrict__ bias)
{
    int i = blockIdx.x * blockDim.x + threadIdx.x;   // of 262144 float4s, N=1024
    float4 a = p0[i], b = p1[i];
    int c0 = (i << 2) & 1023;
    float4 o;
    o.x = a.x + b.x + bias[c0];
    o.y = a.y + b.y + bias[c0 + 1];
    o.z = a.z + b.z + bias[c0 + 2];
    o.w = a.w + b.w + bias[c0 + 3];
    out[i] = o;
}

// ---------------------------------------------------------------------------
// mma.sync bf16 split GEMM: C[M,N] = A[M,K]*B[N,K]^T + bias
//   C ~= Ahi*Bhi + Alo*Bhi + Ahi*Blo   (fp32 accumulate, pass-major ordering)
// CTA tile 128x128, BK=64, 256 threads (8 warps, 2m x 4n, warp tile 64x32)
// Row-padded SMEM (144B stride), 3-stage cp.async pipeline (single sync/chunk).
// MODE 0: relu + bf16 hi/lo outputs; MODE 2: split-K fp32 partial (blockIdx.z half).
// ---------------------------------------------------------------------------
#define ROWB    144
#define TILEB   18432          // 128 * 144
#define BUFB    73728          // 4 tiles
#define MG_SMEM 221184         // 3 buffers (216 KB)

__device__ __forceinline__ void stage_tile(const __nv_bfloat16* __restrict__ g,
                                           int row0, int k0, int ld, uint32_t sdst)
{
    int tid = threadIdx.x;
    #pragma unroll
    for (int i = 0; i < 4; i++) {
        int s = tid + (i << 8);
        int r = s >> 3, sub = s & 7;
        cp16(sdst + (uint32_t)(r * ROWB + sub * 16),
             g + (size_t)(row0 + r) * ld + k0 + sub * 8);
    }
}

__device__ __forceinline__ void stage_buf(
    const __nv_bfloat16* Ah, const __nv_bfloat16* Al,
    const __nv_bfloat16* Bh, const __nv_bfloat16* Bl,
    int bm, int bn, int k0, int ld, uint32_t sbase)
{
    stage_tile(Ah, bm, k0, ld, sbase);
    stage_tile(Al, bm, k0, ld, sbase + TILEB);
    stage_tile(Bh, bn, k0, ld, sbase + 2 * TILEB);
    stage_tile(Bl, bn, k0, ld, sbase + 3 * TILEB);
}

template<int MODE>
__global__ void __launch_bounds__(256, 1) k_mgemm(
    const __nv_bfloat16* __restrict__ Ah, const __nv_bfloat16* __restrict__ Al,
    const __nv_bfloat16* __restrict__ Bh, const __nv_bfloat16* __restrict__ Bl,
    const float* __restrict__ bias,
    __nv_bfloat16* __restrict__ Oh, __nv_bfloat16* __restrict__ Ol,
    float* __restrict__ Of, float* __restrict__ Of2, int N, int ld, int Klen)
{
    extern __shared__ char smem[];
    const uint32_t sb = smem_u32(smem);
    const int tid = threadIdx.x, lane = tid & 31, wid = tid >> 5;
    const int wm = wid & 1, wn = wid >> 1;
    const int bm = blockIdx.y << 7, bn = blockIdx.x << 7;

    if (MODE == 2) {
        size_t koff = (size_t)blockIdx.z * (size_t)Klen;
        Ah += koff; Al += koff; Bh += koff; Bl += koff;
        if (blockIdx.z) Of = Of2;
    }

    float acc[4][4][4];
    #pragma unroll
    for (int f = 0; f < 4; f++)
        #pragma unroll
        for (int g = 0; g < 4; g++)
            #pragma unroll
            for (int v = 0; v < 4; v++) acc[f][g][v] = 0.f;

    const int nc = Klen >> 6;
    stage_buf(Ah, Al, Bh, Bl, bm, bn, 0, ld, sb);
    CP_COMMIT();
    stage_buf(Ah, Al, Bh, Bl, bm, bn, 64, ld, sb + BUFB);
    CP_COMMIT();

    const int arow = wm * 64 + (lane & 15);
    const int acolb = ((lane >> 4) << 3) * 2;
    const int brow = wn * 32 + (lane & 7) + (((lane >> 4) & 1) << 3);
    const int bcolb = (((lane >> 3) & 1) << 3) * 2;

    for (int i = 0; i < nc; i++) {
        if (i < nc - 1) asm volatile("cp.async.wait_group 1;" ::: "memory");
        else           asm volatile("cp.async.wait_group 0;" ::: "memory");
        __syncthreads();

        // prefetch chunk i+2 into the buffer last read at chunk i-1 (safe: sync above)
        if (i + 2 < nc) {
            uint32_t sd = sb + (uint32_t)((i + 2) % 3) * BUFB;
            stage_buf(Ah, Al, Bh, Bl, bm, bn, (i + 2) << 6, ld, sd);
            CP_COMMIT();
        }

        const uint32_t base = sb + (uint32_t)(i % 3) * BUFB;
        #pragma unroll
        for (int kk = 0; kk < 4; kk++) {
            uint32_t Ahf[4][4], Alf[4][4], Bhf[2][4], Blf[2][4];
            const uint32_t ak = (uint32_t)(kk * 32) + acolb;
            const uint32_t bk = (uint32_t)(kk * 32) + bcolb;
            #pragma unroll
            for (int f = 0; f < 4; f++) {
                uint32_t ra = base + (uint32_t)((arow + f * 16) * ROWB) + ak;
                ldm_x4(Ahf[f], ra);
                ldm_x4(Alf[f], ra + TILEB);
            }
            #pragma unroll
            for (int p = 0; p < 2; p++) {
                uint32_t rb = base + 2u * TILEB + (uint32_t)((brow + p * 16) * ROWB) + bk;
                ldm_x4(Bhf[p], rb);
                ldm_x4(Blf[p], rb + TILEB);
            }
            // pass-major: 16 independent mmas per pass (RAW distance 16)
            #pragma unroll
            for (int f = 0; f < 4; f++)
                #pragma unroll
                for (int g = 0; g < 4; g++)
                    mma_bf16(acc[f][g], Ahf[f], &Bhf[g >> 1][(g & 1) << 1]);
            #pragma unroll
            for (int f = 0; f < 4; f++)
                #pragma unroll
                for (int g = 0; g < 4; g++)
                    mma_bf16(acc[f][g], Alf[f], &Bhf[g >> 1][(g & 1) << 1]);
            #pragma unroll
            for (int f = 0; f < 4; f++)
                #pragma unroll
                for (int g = 0; g < 4; g++)
                    mma_bf16(acc[f][g], Ahf[f], &Blf[g >> 1][(g & 1) << 1]);
        }
    }

    // epilogue
    #pragma unroll
    for (int f = 0; f < 4; f++) {
        #pragma unroll
        for (int g = 0; g < 4; g++) {
            int r0 = bm + wm * 64 + f * 16 + (lane >> 2);
            int c0 = bn + wn * 32 + g * 8 + ((lane & 3) << 1);
            float bv0 = (MODE == 2) ? 0.f : bias[c0];
            float bv1 = (MODE == 2) ? 0.f : bias[c0 + 1];
            #pragma unroll
            for (int h = 0; h < 2; h++) {
                int r = r0 + h * 8;
                float v0 = acc[f][g][2 * h + 0] + bv0;
                float v1 = acc[f][g][2 * h + 1] + bv1;
                if (MODE == 0) {
                    v0 = fmaxf(v0, 0.f); v1 = fmaxf(v1, 0.f);
                    __nv_bfloat16 h0 = __float2bfloat16(v0), h1 = __float2bfloat16(v1);
                    __nv_bfloat16 l0 = __float2bfloat16(v0 - __bfloat162float(h0));
                    __nv_bfloat16 l1 = __float2bfloat16(v1 - __bfloat162float(h1));
                    ushort2 uh = make_ushort2(__bfloat16_as_ushort(h0), __bfloat16_as_ushort(h1));
                    ushort2 ul = make_ushort2(__bfloat16_as_ushort(l0), __bfloat16_as_ushort(l1));
                    *(ushort2*)(Oh + (size_t)r * N + c0) = uh;
                    *(ushort2*)(Ol + (size_t)r * N + c0) = ul;
                } else {
                    float2 o = make_float2(v0, v1);
                    *(float2*)(Of + (size_t)r * N + c0) = o;
                }
            }
        }
    }
}

// ---------------------------------------------------------------------------
// Launch
// ---------------------------------------------------------------------------
extern "C" void kernel_launch(void* const* d_in, const int* in_sizes, int n_in,
                              void* d_out, int out_size)
{
    const float* x  = (const float*)d_in[0];
    const float* W1 = (const float*)d_in[1];
    const float* b1 = (const float*)d_in[2];
    const float* W2 = (const float*)d_in[3];
    const float* b2 = (const float*)d_in[4];
    const float* W3 = (const float*)d_in[5];
    const float* b3 = (const float*)d_in[6];
    const float4* s0 = (const float4*)d_in[7];
    const float4* s1 = (const float4*)d_in[8];
    const float4* s2 = (const float4*)d_in[9];
    const float4* s3 = (const float4*)d_in[10];
    const float4* s4 = (const float4*)d_in[11];
    const float4* s5 = (const float4*)d_in[12];

    void* p;
    cudaGetSymbolAddress(&p, g_wh);  __nv_bfloat16* wh  = (__nv_bfloat16*)p;
    cudaGetSymbolAddress(&p, g_wl);  __nv_bfloat16* wl  = (__nv_bfloat16*)p;
    cudaGetSymbolAddress(&p, g_xh);  __nv_bfloat16* xh  = (__nv_bfloat16*)p;
    cudaGetSymbolAddress(&p, g_xl);  __nv_bfloat16* xl  = (__nv_bfloat16*)p;
    cudaGetSymbolAddress(&p, g_h1h); __nv_bfloat16* h1h = (__nv_bfloat16*)p;
    cudaGetSymbolAddress(&p, g_h1l); __nv_bfloat16* h1l = (__nv_bfloat16*)p;
    cudaGetSymbolAddress(&p, g_h2h); __nv_bfloat16* h2h = (__nv_bfloat16*)p;
    cudaGetSymbolAddress(&p, g_h2l); __nv_bfloat16* h2l = (__nv_bfloat16*)p;
    cudaGetSymbolAddress(&p, g_p0);  float* p0 = (float*)p;
    cudaGetSymbolAddress(&p, g_p1);  float* p1 = (float*)p;
    cudaGetSymbolAddress(&p, g_mb);  float* mb = (float*)p;

    cudaFuncSetAttribute(k_mgemm<0>, cudaFuncAttributeMaxDynamicSharedMemorySize, MG_SMEM);
    cudaFuncSetAttribute(k_mgemm<2>, cudaFuncAttributeMaxDynamicSharedMemorySize, MG_SMEM);

    // ---- selection: level-1 hist + scan, compact selected bin, finish ----
    k_zero<<<1, 256>>>();
    k_hist1<<<1024, 256>>>(s0, s1, s2, s3, s4, s5);
    k_scan1<<<1, 256>>>();
    k_compact<<<1024, 256>>>(s0, s1, s2, s3, s4, s5);
    k_finish<<<1, 1024>>>();

    // ---- x split (131072 pairs) ----
    k_split<<<512, 256>>>((const float4*)x, xh, xl, 131072);

    // ---- layer 1 ----
    k_applyw<<<2048, 256>>>((const float4*)W1, s0, wh, wl, 524288, 0u);
    k_applyb<<<4, 256>>>((const float4*)b1, s1, (float4*)mb, 1024, (unsigned)E0);
    k_mgemm<0><<<dim3(32, 8), 256, MG_SMEM>>>(xh, xl, wh, wl, mb, h1h, h1l, nullptr, nullptr, 4096, 1024, 1024);

    // ---- layer 2 ----
    k_applyw<<<8192, 256>>>((const float4*)W2, s2, wh, wl, 2097152, (unsigned)E1);
    k_applyb<<<4, 256>>>((const float4*)b2, s3, (float4*)mb, 1024, (unsigned)E2);
    k_mgemm<0><<<dim3(32, 8), 256, MG_SMEM>>>(h1h, h1l, wh, wl, mb, h2h, h2l, nullptr, nullptr, 4096, 4096, 4096);

    // ---- layer 3 (split-K=2 across blockIdx.z, then reduce with bias) ----
    k_applyw<<<2048, 256>>>((const float4*)W3, s4, wh, wl, 524288, (unsigned)E3);
    k_applyb<<<1, 256>>>((const float4*)b3, s5, (float4*)mb, 256, (unsigned)E4);
    k_mgemm<2><<<dim3(8, 8, 2), 256, MG_SMEM>>>(h2h, h2l, wh, wl, mb, nullptr, nullptr, p0, p1, 1024, 4096, 2048);
    k_reduce3<<<1024, 256>>>((float4*)d_out, (const float4*)p0, (const float4*)p1, mb);
}